// round 6
// baseline (speedup 1.0000x reference)
#include <cuda_runtime.h>
#include <cuda_bf16.h>
#include <cstdint>

#define BSZ    8
#define TLEN   4096
#define DH     256
#define NPAIR  128
#define LCHUNK 128
#define NCHUNK (TLEN / LCHUNK)   // 32
#define SUB    16                // steps per sub-chunk (8 sub-chunks per chunk)

// ---------------- device scratch (static; no allocations) ----------------
__device__ __align__(16) __nv_bfloat16 g_Whi[DH * DH];   // W [n][d]
__device__ __align__(16) __nv_bfloat16 g_Wlo[DH * DH];
__device__ __align__(16) __nv_bfloat16 g_Chi[DH * DH];   // C_eff [dout][n]
__device__ __align__(16) __nv_bfloat16 g_Clo[DH * DH];
__device__ __align__(16) __nv_bfloat16 g_UThi[BSZ * TLEN * DH];  // u^T [b][t][d]
__device__ __align__(16) __nv_bfloat16 g_UTlo[BSZ * TLEN * DH];
__device__ __align__(16) float         g_V   [BSZ * TLEN * DH];  // [b][t][n]
__device__ __align__(16) __nv_bfloat16 g_Shi[BSZ * TLEN * DH];   // [b][t][n]
__device__ __align__(16) __nv_bfloat16 g_Slo[BSZ * TLEN * DH];
__device__ float2 g_lam  [NPAIR];            // lambda
__device__ float2 g_lam16[NPAIR];            // lambda^16
__device__ float2 g_lamPow[NCHUNK][NPAIR];   // lambda^(128*j)
__device__ float2 g_agg  [BSZ * NCHUNK * NPAIR];  // local chunk aggregates
__device__ int    g_flag [BSZ * NCHUNK];

// ---------------- PTX helpers (all sm_80+ portable) ----------------
__device__ __forceinline__ uint32_t smem_u32(const void* p) {
    uint32_t a;
    asm("{ .reg .u64 t; cvta.to.shared.u64 t, %1; cvt.u32.u64 %0, t; }" : "=r"(a) : "l"(p));
    return a;
}
__device__ __forceinline__ void cpa16(uint32_t dst, const void* src) {
    asm volatile("cp.async.cg.shared.global [%0], [%1], 16;" :: "r"(dst), "l"(src));
}
__device__ __forceinline__ void cpa_commit() { asm volatile("cp.async.commit_group;"); }

__device__ __forceinline__ void ldmx4(uint32_t* r, uint32_t addr) {
    asm volatile("ldmatrix.sync.aligned.m8n8.x4.shared.b16 {%0,%1,%2,%3}, [%4];"
                 : "=r"(r[0]), "=r"(r[1]), "=r"(r[2]), "=r"(r[3]) : "r"(addr));
}
__device__ __forceinline__ void mma_bf16(float* c, const uint32_t* a, uint32_t b0, uint32_t b1) {
    asm volatile("mma.sync.aligned.m16n8k16.row.col.f32.bf16.bf16.f32 "
                 "{%0,%1,%2,%3}, {%4,%5,%6,%7}, {%8,%9}, {%0,%1,%2,%3};"
                 : "+f"(c[0]), "+f"(c[1]), "+f"(c[2]), "+f"(c[3])
                 : "r"(a[0]), "r"(a[1]), "r"(a[2]), "r"(a[3]), "r"(b0), "r"(b1));
}
__device__ __forceinline__ uint32_t swz64(int r, int ch) {
    return (uint32_t)(r * 64 + ((ch ^ ((r >> 1) & 3)) << 4));
}

// ============================================================================
// Setup: expm(skew) per head, fold into W=[n][d] and C_eff=[dout][n] (bf16 hi/lo)
// ============================================================================
__global__ void setup_kernel(const float* __restrict__ thetas_log,
                             const float* __restrict__ P_param,
                             const float* __restrict__ B_param,
                             const float* __restrict__ C,
                             const float* __restrict__ gamma_log)
{
    int h = blockIdx.x, tid = threadIdx.x;
    __shared__ double sA[16], sEd[16], sTm[16], sTmp[16];
    __shared__ float  sRed[256], sEf[16], sNrm;

    if (h == 0 && tid < BSZ * NCHUNK) g_flag[tid] = 0;

    float part = 0.f;
    for (int i = tid; i < 1024; i += 256) {
        float v = B_param[h * 1024 + i];
        part += v * v;
    }
    sRed[tid] = part;
    __syncthreads();
    for (int s = 128; s > 0; s >>= 1) {
        if (tid < s) sRed[tid] += sRed[tid + s];
        __syncthreads();
    }
    if (tid < 16) {
        int i = tid >> 2, j = tid & 3;
        sA[tid]  = (double)P_param[h * 16 + tid] - (double)P_param[h * 16 + j * 4 + i];
        sEd[tid] = (i == j) ? 1.0 : 0.0;
        sTm[tid] = sEd[tid];
    }
    __syncthreads();
    for (int k = 1; k <= 24; ++k) {
        if (tid < 16) {
            int i = tid >> 2, j = tid & 3;
            double acc = 0.0;
#pragma unroll
            for (int m = 0; m < 4; m++) acc += sTm[i * 4 + m] * sA[m * 4 + j];
            sTmp[tid] = acc / (double)k;
        }
        __syncthreads();
        if (tid < 16) { sTm[tid] = sTmp[tid]; sEd[tid] += sTmp[tid]; }
        __syncthreads();
    }
    if (tid == 0) {
        double gl = (double)gamma_log[h], eg = exp(gl), gamma = exp(-eg);
        sNrm = (float)sqrt((1.0 - gamma * gamma) / (double)sRed[0]);
        const double TWO_PI = 6.283185307179586476925286766559;
        for (int j = 0; j < 2; j++) {
            double th = exp((double)thetas_log[h * 2 + j]);
            int p = h * 2 + j;
            g_lam[p] = make_float2((float)(gamma * cos(th)), (float)(gamma * sin(th)));
            double g16 = exp(-16.0 * eg), a16 = fmod(16.0 * th, TWO_PI);
            g_lam16[p] = make_float2((float)(g16 * cos(a16)), (float)(g16 * sin(a16)));
            for (int q = 0; q < NCHUNK; q++) {
                double gq = exp(-128.0 * q * eg);
                double aq = fmod(128.0 * q * th, TWO_PI);
                g_lamPow[q][p] = make_float2((float)(gq * cos(aq)), (float)(gq * sin(aq)));
            }
        }
    }
    if (tid < 16) sEf[tid] = (float)sEd[tid];
    __syncthreads();
    float nrm = sNrm;
    for (int o = tid; o < 1024; o += 256) {
        int N = o >> 8, d = o & 255;
        float w = 0.f;
#pragma unroll
        for (int n = 0; n < 4; n++) w += sEf[N * 4 + n] * B_param[h * 1024 + n * 256 + d];
        w *= nrm;
        __nv_bfloat16 hi = __float2bfloat16_rn(w);
        __nv_bfloat16 lo = __float2bfloat16_rn(w - __bfloat162float(hi));
        g_Whi[(h * 4 + N) * 256 + d] = hi;
        g_Wlo[(h * 4 + N) * 256 + d] = lo;
    }
    for (int o = tid; o < 1024; o += 256) {
        int N = o >> 8, Do = o & 255;
        float c = 0.f;
#pragma unroll
        for (int n = 0; n < 4; n++) c += C[Do * 256 + h * 4 + n] * sEf[N * 4 + n];
        __nv_bfloat16 hi = __float2bfloat16_rn(c);
        __nv_bfloat16 lo = __float2bfloat16_rn(c - __bfloat162float(hi));
        g_Chi[Do * 256 + h * 4 + N] = hi;
        g_Clo[Do * 256 + h * 4 + N] = lo;
    }
}

// ============================================================================
// Transpose u [b][d][t] -> u^T hi/lo bf16 [b][t][d]
// ============================================================================
__global__ __launch_bounds__(256) void transp_kernel(const float* __restrict__ U)
{
    __shared__ float s[64][65];
    int b = blockIdx.z, d0 = blockIdx.y * 64, t0 = blockIdx.x * 64;
    const float* Ub = U + ((long)b * DH + d0) * TLEN;
    int tid = threadIdx.x;
#pragma unroll
    for (int i = 0; i < 4; i++) {
        int lin = tid + i * 256;
        int r = lin >> 4, c4 = (lin & 15) << 2;
        float4 v = *(const float4*)&Ub[(long)r * TLEN + t0 + c4];
        s[r][c4] = v.x; s[r][c4 + 1] = v.y; s[r][c4 + 2] = v.z; s[r][c4 + 3] = v.w;
    }
    __syncthreads();
#pragma unroll
    for (int i = 0; i < 4; i++) {
        int lin = tid + i * 256;
        int tr = lin >> 4, dc = (lin & 15) << 2;
        long oidx = ((long)b * TLEN + t0 + tr) * 256 + d0 + dc;
        __nv_bfloat162 h2a, h2b, l2a, l2b;
        float v0 = s[dc + 0][tr], v1 = s[dc + 1][tr], v2 = s[dc + 2][tr], v3 = s[dc + 3][tr];
        h2a.x = __float2bfloat16_rn(v0); l2a.x = __float2bfloat16_rn(v0 - __bfloat162float(h2a.x));
        h2a.y = __float2bfloat16_rn(v1); l2a.y = __float2bfloat16_rn(v1 - __bfloat162float(h2a.y));
        h2b.x = __float2bfloat16_rn(v2); l2b.x = __float2bfloat16_rn(v2 - __bfloat162float(h2b.x));
        h2b.y = __float2bfloat16_rn(v3); l2b.y = __float2bfloat16_rn(v3 - __bfloat162float(h2b.y));
        *(__nv_bfloat162*)&g_UThi[oidx]     = h2a;
        *(__nv_bfloat162*)&g_UThi[oidx + 2] = h2b;
        *(__nv_bfloat162*)&g_UTlo[oidx]     = l2a;
        *(__nv_bfloat162*)&g_UTlo[oidx + 2] = l2b;
    }
}

// ============================================================================
// mma.sync GEMM. MODE 0: V[b][t][n] = (W @ uT^T)^T.  MODE 1: Y = C_eff @ S^T + D*u.
// ============================================================================
template <int MODE>
__global__ __launch_bounds__(256, 2) void mma_gemm_kernel(const float* __restrict__ U,
                                                          const float* __restrict__ Dvec,
                                                          float* __restrict__ Yout)
{
    __shared__ __align__(128) __nv_bfloat16 sA[2][128 * 32];
    __shared__ __align__(128) __nv_bfloat16 sB[2][128 * 32];

    int tid = threadIdx.x, lid = tid & 31, wid = tid >> 5;
    int warp_m = wid & 1, warp_t = wid >> 1;
    int b = blockIdx.z, t0 = blockIdx.x * 128, m0 = blockIdx.y * 128;

    const __nv_bfloat16* Ahi = (MODE == 0) ? g_Whi  : g_Chi;
    const __nv_bfloat16* Alo = (MODE == 0) ? g_Wlo  : g_Clo;
    const __nv_bfloat16* Bhi = (MODE == 0) ? g_UThi : g_Shi;
    const __nv_bfloat16* Blo = (MODE == 0) ? g_UTlo : g_Slo;
    long brow0 = (long)b * TLEN + t0;

    uint32_t aB[2] = { smem_u32(sA[0]), smem_u32(sA[1]) };
    uint32_t bB[2] = { smem_u32(sB[0]), smem_u32(sB[1]) };

    float acc[4][4][4];
#pragma unroll
    for (int mi = 0; mi < 4; mi++)
#pragma unroll
        for (int j = 0; j < 4; j++)
#pragma unroll
            for (int q = 0; q < 4; q++) acc[mi][j][q] = 0.f;

    int qa = tid;
    auto load_chunk = [&](int cs, int buf) {
        int pass = cs >> 3, k0 = (cs & 7) * 32;
        const __nv_bfloat16* As = (pass == 2) ? Alo : Ahi;
        const __nv_bfloat16* Bs = (pass == 1) ? Blo : Bhi;
#pragma unroll
        for (int i = 0; i < 2; i++) {
            int q = qa + i * 256;
            int r = q >> 2, ch = q & 3;
            cpa16(aB[buf] + swz64(r, ch), As + (long)(m0 + r) * 256 + k0 + ch * 8);
        }
#pragma unroll
        for (int i = 0; i < 2; i++) {
            int q = qa + i * 256;
            int r = q >> 2, ch = q & 3;
            cpa16(bB[buf] + swz64(r, ch), Bs + (brow0 + r) * 256 + k0 + ch * 8);
        }
        cpa_commit();
    };

    load_chunk(0, 0);
    for (int cs = 0; cs < 24; cs++) {
        int buf = cs & 1;
        if (cs + 1 < 24) {
            load_chunk(cs + 1, buf ^ 1);
            asm volatile("cp.async.wait_group 1;" ::: "memory");
        } else {
            asm volatile("cp.async.wait_group 0;" ::: "memory");
        }
        __syncthreads();

#pragma unroll
        for (int kk = 0; kk < 2; kk++) {
            int chb = kk * 2 + (lid >> 4);
            uint32_t bf[2][4];
#pragma unroll
            for (int nb = 0; nb < 2; nb++) {
                int tr = warp_t * 32 + nb * 16 + (lid & 15);
                ldmx4(bf[nb], bB[buf] + swz64(tr, chb));
            }
            uint32_t af[4][4];
#pragma unroll
            for (int mi = 0; mi < 4; mi++) {
                int r = warp_m * 64 + mi * 16 + (lid & 15);
                ldmx4(af[mi], aB[buf] + swz64(r, chb));
            }
#pragma unroll
            for (int mi = 0; mi < 4; mi++)
#pragma unroll
                for (int j = 0; j < 4; j++)
                    mma_bf16(acc[mi][j], af[mi], bf[j >> 1][j & 1], bf[j >> 1][2 + (j & 1)]);
        }
        __syncthreads();
    }

    int cbase = t0 + warp_t * 32 + 2 * (lid & 3);
#pragma unroll
    for (int mi = 0; mi < 4; mi++) {
#pragma unroll
        for (int h = 0; h < 2; h++) {
            int row = m0 + warp_m * 64 + mi * 16 + (lid >> 2) + h * 8;
            if (MODE == 0) {
#pragma unroll
                for (int j = 0; j < 4; j++) {
                    long basev = ((long)b * TLEN + cbase + j * 8) * 256 + row;
                    g_V[basev]       = acc[mi][j][2 * h];
                    g_V[basev + 256] = acc[mi][j][2 * h + 1];
                }
            } else {
                float dv = Dvec[row];
                const float* urow = U    + ((long)b * DH + row) * TLEN;
                float*       yrow = Yout + ((long)b * DH + row) * TLEN;
#pragma unroll
                for (int j = 0; j < 4; j++) {
                    float2 u2 = *(const float2*)&urow[cbase + j * 8];
                    *(float2*)&yrow[cbase + j * 8] =
                        make_float2(acc[mi][j][2 * h]     + dv * u2.x,
                                    acc[mi][j][2 * h + 1] + dv * u2.y);
                }
            }
        }
    }
}

// ============================================================================
// Scan over t on V [b][t][n]. Block = 1024 threads = 128 pairs x 8 sub-chunks
// of 16 steps (LCHUNK=128). V register-cached; all-predecessor lookback via
// published LOCAL aggregates + lambda^(128j) table (no serial carry chain).
// ============================================================================
__global__ __launch_bounds__(1024, 1) void scan_kernel()
{
    __shared__ float2 sLoc[8][NPAIR];
    __shared__ float2 sExc[8][NPAIR];
    __shared__ float2 sAgg[NPAIR];
    __shared__ float2 sE[NPAIR];

    int b = blockIdx.x & 7, chunk = blockIdx.x >> 3;
    int tid = threadIdx.x, p = tid & 127, sc = tid >> 7;
    float2 lam = g_lam[p];
    float lc = lam.x, ls = lam.y;
    float2 l16 = g_lam16[p];
    long vbase = ((long)b * TLEN + chunk * LCHUNK + sc * SUB) * 256 + 2 * p;

    // phase 1: load V into registers, local sub-chunk scan from zero
    float2 v[SUB];
    float s0 = 0.f, s1 = 0.f;
#pragma unroll
    for (int t = 0; t < SUB; t++) {
        v[t] = *(const float2*)&g_V[vbase + (long)t * 256];
        float n0 = fmaf(lc, s0, fmaf(-ls, s1, v[t].x));
        float n1 = fmaf(ls, s0, fmaf( lc, s1, v[t].y));
        s0 = n0; s1 = n1;
    }
    sLoc[sc][p] = make_float2(s0, s1);
    __syncthreads();

    // combine sub-chunk carries, publish LOCAL chunk aggregate
    int idx = b * NCHUNK + chunk;
    if (tid < NPAIR) {
        float i0 = 0.f, i1 = 0.f;
#pragma unroll
        for (int k = 0; k < 8; k++) {
            sExc[k][p] = make_float2(i0, i1);
            float2 lo = sLoc[k][p];
            float a0 = fmaf(l16.x, i0, fmaf(-l16.y, i1, lo.x));
            float a1 = fmaf(l16.y, i0, fmaf( l16.x, i1, lo.y));
            i0 = a0; i1 = a1;
        }
        sAgg[p] = make_float2(i0, i1);
        __stcg(&g_agg[idx * NPAIR + p], make_float2(i0, i1));
    }
    __syncthreads();
    if (tid == 0) {
        __threadfence();
        atomicExch(&g_flag[idx], 1);
        // wait for ALL predecessor chunks of this batch
        for (int k = 0; k < chunk; k++) {
            while (atomicAdd(&g_flag[b * NCHUNK + k], 0) == 0) __nanosleep(40);
        }
    }
    __syncthreads();

    // E = sum_{k<chunk} lambda^(128*(chunk-1-k)) * A_k
    if (tid < NPAIR) {
        float e0 = 0.f, e1 = 0.f;
        for (int k = 0; k < chunk; k++) {
            float2 pw = g_lamPow[chunk - 1 - k][p];
            float2 a = __ldcg(&g_agg[(b * NCHUNK + k) * NPAIR + p]);
            e0 = fmaf(pw.x, a.x, fmaf(-pw.y, a.y, e0));
            e1 = fmaf(pw.y, a.x, fmaf( pw.x, a.y, e1));
        }
        sE[p] = make_float2(e0, e1);
    }
    __syncthreads();

    // start state = lambda^(16*sc) * E + exclusive_within(sc)
    float2 E = sE[p];
    float m0 = 1.f, m1 = 0.f;
    for (int i = 0; i < sc; i++) {
        float a0 = m0 * l16.x - m1 * l16.y;
        float a1 = m0 * l16.y + m1 * l16.x;
        m0 = a0; m1 = a1;
    }
    float2 ex = sExc[sc][p];
    s0 = fmaf(m0, E.x, fmaf(-m1, E.y, ex.x));
    s1 = fmaf(m1, E.x, fmaf( m0, E.y, ex.y));

    // phase 2: rescan from registers + emit bf16 hi/lo
#pragma unroll
    for (int t = 0; t < SUB; t++) {
        float n0 = fmaf(lc, s0, fmaf(-ls, s1, v[t].x));
        float n1 = fmaf(ls, s0, fmaf( lc, s1, v[t].y));
        s0 = n0; s1 = n1;
        __nv_bfloat162 h2, l2;
        h2.x = __float2bfloat16_rn(s0); l2.x = __float2bfloat16_rn(s0 - __bfloat162float(h2.x));
        h2.y = __float2bfloat16_rn(s1); l2.y = __float2bfloat16_rn(s1 - __bfloat162float(h2.y));
        *(__nv_bfloat162*)&g_Shi[vbase + (long)t * 256] = h2;
        *(__nv_bfloat162*)&g_Slo[vbase + (long)t * 256] = l2;
    }
}

// ============================================================================
extern "C" void kernel_launch(void* const* d_in, const int* in_sizes, int n_in,
                              void* d_out, int out_size)
{
    const float* u          = (const float*)d_in[0];
    const float* thetas_log = (const float*)d_in[1];
    const float* P_param    = (const float*)d_in[2];
    const float* B_param    = (const float*)d_in[3];
    const float* C          = (const float*)d_in[4];
    const float* Dv         = (const float*)d_in[5];
    const float* gamma_log  = (const float*)d_in[6];
    float* Y = (float*)d_out;

    setup_kernel<<<64, 256>>>(thetas_log, P_param, B_param, C, gamma_log);
    transp_kernel<<<dim3(TLEN / 64, DH / 64, BSZ), 256>>>(u);
    mma_gemm_kernel<0><<<dim3(TLEN / 128, 2, BSZ), 256>>>(nullptr, nullptr, nullptr);
    scan_kernel<<<BSZ * NCHUNK, 1024>>>();
    mma_gemm_kernel<1><<<dim3(TLEN / 128, 2, BSZ), 256>>>(u, Dv, Y);
}

// round 7
// speedup vs baseline: 1.8042x; 1.8042x over previous
#include <cuda_runtime.h>
#include <cuda_bf16.h>
#include <cstdint>

#define BSZ    8
#define TLEN   4096
#define DH     256
#define NPAIR  128
#define LCHUNK 128
#define NCHUNK (TLEN / LCHUNK)   // 32
#define SUB    16                // steps per sub-chunk (8 sub-chunks per chunk)

// ---------------- device scratch (static; no allocations) ----------------
__device__ __align__(16) __nv_bfloat16 g_Whi[DH * DH];   // W [n][d]
__device__ __align__(16) __nv_bfloat16 g_Wlo[DH * DH];
__device__ __align__(16) __nv_bfloat16 g_Chi[DH * DH];   // C_eff [dout][n]
__device__ __align__(16) __nv_bfloat16 g_Clo[DH * DH];
__device__ __align__(16) __nv_bfloat16 g_UThi[BSZ * TLEN * DH];  // u^T [b][t][d]
__device__ __align__(16) __nv_bfloat16 g_UTlo[BSZ * TLEN * DH];
__device__ __align__(16) float         g_V   [BSZ * TLEN * DH];  // [b][t][n]
__device__ __align__(16) __nv_bfloat16 g_Shi[BSZ * TLEN * DH];   // [b][t][n]
__device__ __align__(16) __nv_bfloat16 g_Slo[BSZ * TLEN * DH];
__device__ float2 g_lam  [NPAIR];            // lambda
__device__ float2 g_lam16[NPAIR];            // lambda^16
__device__ float2 g_lamPow[NCHUNK][NPAIR];   // lambda^(128*j)
__device__ float2 g_agg  [BSZ * NCHUNK * NPAIR];  // local chunk aggregates
__device__ int    g_flag [BSZ * NCHUNK];

// ---------------- PTX helpers (all sm_80+ portable) ----------------
__device__ __forceinline__ uint32_t smem_u32(const void* p) {
    uint32_t a;
    asm("{ .reg .u64 t; cvta.to.shared.u64 t, %1; cvt.u32.u64 %0, t; }" : "=r"(a) : "l"(p));
    return a;
}
__device__ __forceinline__ void cpa16(uint32_t dst, const void* src) {
    asm volatile("cp.async.cg.shared.global [%0], [%1], 16;" :: "r"(dst), "l"(src));
}
__device__ __forceinline__ void cpa_commit() { asm volatile("cp.async.commit_group;"); }

__device__ __forceinline__ void ldmx4(uint32_t* r, uint32_t addr) {
    asm volatile("ldmatrix.sync.aligned.m8n8.x4.shared.b16 {%0,%1,%2,%3}, [%4];"
                 : "=r"(r[0]), "=r"(r[1]), "=r"(r[2]), "=r"(r[3]) : "r"(addr));
}
__device__ __forceinline__ void mma_bf16(float* c, const uint32_t* a, uint32_t b0, uint32_t b1) {
    asm volatile("mma.sync.aligned.m16n8k16.row.col.f32.bf16.bf16.f32 "
                 "{%0,%1,%2,%3}, {%4,%5,%6,%7}, {%8,%9}, {%0,%1,%2,%3};"
                 : "+f"(c[0]), "+f"(c[1]), "+f"(c[2]), "+f"(c[3])
                 : "r"(a[0]), "r"(a[1]), "r"(a[2]), "r"(a[3]), "r"(b0), "r"(b1));
}
__device__ __forceinline__ uint32_t swz64(int r, int ch) {
    return (uint32_t)(r * 64 + ((ch ^ ((r >> 1) & 3)) << 4));
}

// ============================================================================
// Setup: expm(skew) per head, fold into W=[n][d] and C_eff=[dout][n] (bf16 hi/lo).
// Lambda power table parallelized across 64 threads (was serial on tid 0 —
// that serial fp64 transcendental chain was the round-6 regression).
// ============================================================================
__global__ void setup_kernel(const float* __restrict__ thetas_log,
                             const float* __restrict__ P_param,
                             const float* __restrict__ B_param,
                             const float* __restrict__ C,
                             const float* __restrict__ gamma_log)
{
    int h = blockIdx.x, tid = threadIdx.x;
    __shared__ double sA[16], sEd[16], sTm[16], sTmp[16];
    __shared__ float  sRed[256], sEf[16], sNrm;
    __shared__ double sEg;

    if (h == 0 && tid < BSZ * NCHUNK) g_flag[tid] = 0;

    float part = 0.f;
    for (int i = tid; i < 1024; i += 256) {
        float v = B_param[h * 1024 + i];
        part += v * v;
    }
    sRed[tid] = part;
    __syncthreads();
    for (int s = 128; s > 0; s >>= 1) {
        if (tid < s) sRed[tid] += sRed[tid + s];
        __syncthreads();
    }
    if (tid < 16) {
        int i = tid >> 2, j = tid & 3;
        sA[tid]  = (double)P_param[h * 16 + tid] - (double)P_param[h * 16 + j * 4 + i];
        sEd[tid] = (i == j) ? 1.0 : 0.0;
        sTm[tid] = sEd[tid];
    }
    __syncthreads();
    for (int k = 1; k <= 24; ++k) {
        if (tid < 16) {
            int i = tid >> 2, j = tid & 3;
            double acc = 0.0;
#pragma unroll
            for (int m = 0; m < 4; m++) acc += sTm[i * 4 + m] * sA[m * 4 + j];
            sTmp[tid] = acc / (double)k;
        }
        __syncthreads();
        if (tid < 16) { sTm[tid] = sTmp[tid]; sEd[tid] += sTmp[tid]; }
        __syncthreads();
    }
    const double TWO_PI = 6.283185307179586476925286766559;
    if (tid == 0) {
        double gl = (double)gamma_log[h], eg = exp(gl), gamma = exp(-eg);
        sEg = eg;
        sNrm = (float)sqrt((1.0 - gamma * gamma) / (double)sRed[0]);
        for (int j = 0; j < 2; j++) {
            double th = exp((double)thetas_log[h * 2 + j]);
            int p = h * 2 + j;
            g_lam[p] = make_float2((float)(gamma * cos(th)), (float)(gamma * sin(th)));
            double g16 = exp(-16.0 * eg), a16 = fmod(16.0 * th, TWO_PI);
            g_lam16[p] = make_float2((float)(g16 * cos(a16)), (float)(g16 * sin(a16)));
        }
    }
    if (tid < 16) sEf[tid] = (float)sEd[tid];
    __syncthreads();
    // lambda^(128*q) table: one (pair, chunk) entry per thread — parallel fp64.
    if (tid < 2 * NCHUNK) {
        int j = tid & 1, q = tid >> 1;
        double th = exp((double)thetas_log[h * 2 + j]);
        double gq = exp(-128.0 * (double)q * sEg);
        double aq = fmod(128.0 * (double)q * th, TWO_PI);
        g_lamPow[q][h * 2 + j] = make_float2((float)(gq * cos(aq)), (float)(gq * sin(aq)));
    }
    float nrm = sNrm;
    for (int o = tid; o < 1024; o += 256) {
        int N = o >> 8, d = o & 255;
        float w = 0.f;
#pragma unroll
        for (int n = 0; n < 4; n++) w += sEf[N * 4 + n] * B_param[h * 1024 + n * 256 + d];
        w *= nrm;
        __nv_bfloat16 hi = __float2bfloat16_rn(w);
        __nv_bfloat16 lo = __float2bfloat16_rn(w - __bfloat162float(hi));
        g_Whi[(h * 4 + N) * 256 + d] = hi;
        g_Wlo[(h * 4 + N) * 256 + d] = lo;
    }
    for (int o = tid; o < 1024; o += 256) {
        int N = o >> 8, Do = o & 255;
        float c = 0.f;
#pragma unroll
        for (int n = 0; n < 4; n++) c += C[Do * 256 + h * 4 + n] * sEf[N * 4 + n];
        __nv_bfloat16 hi = __float2bfloat16_rn(c);
        __nv_bfloat16 lo = __float2bfloat16_rn(c - __bfloat162float(hi));
        g_Chi[Do * 256 + h * 4 + N] = hi;
        g_Clo[Do * 256 + h * 4 + N] = lo;
    }
}

// ============================================================================
// Transpose u [b][d][t] -> u^T hi/lo bf16 [b][t][d]
// ============================================================================
__global__ __launch_bounds__(256) void transp_kernel(const float* __restrict__ U)
{
    __shared__ float s[64][65];
    int b = blockIdx.z, d0 = blockIdx.y * 64, t0 = blockIdx.x * 64;
    const float* Ub = U + ((long)b * DH + d0) * TLEN;
    int tid = threadIdx.x;
#pragma unroll
    for (int i = 0; i < 4; i++) {
        int lin = tid + i * 256;
        int r = lin >> 4, c4 = (lin & 15) << 2;
        float4 v = *(const float4*)&Ub[(long)r * TLEN + t0 + c4];
        s[r][c4] = v.x; s[r][c4 + 1] = v.y; s[r][c4 + 2] = v.z; s[r][c4 + 3] = v.w;
    }
    __syncthreads();
#pragma unroll
    for (int i = 0; i < 4; i++) {
        int lin = tid + i * 256;
        int tr = lin >> 4, dc = (lin & 15) << 2;
        long oidx = ((long)b * TLEN + t0 + tr) * 256 + d0 + dc;
        __nv_bfloat162 h2a, h2b, l2a, l2b;
        float v0 = s[dc + 0][tr], v1 = s[dc + 1][tr], v2 = s[dc + 2][tr], v3 = s[dc + 3][tr];
        h2a.x = __float2bfloat16_rn(v0); l2a.x = __float2bfloat16_rn(v0 - __bfloat162float(h2a.x));
        h2a.y = __float2bfloat16_rn(v1); l2a.y = __float2bfloat16_rn(v1 - __bfloat162float(h2a.y));
        h2b.x = __float2bfloat16_rn(v2); l2b.x = __float2bfloat16_rn(v2 - __bfloat162float(h2b.x));
        h2b.y = __float2bfloat16_rn(v3); l2b.y = __float2bfloat16_rn(v3 - __bfloat162float(h2b.y));
        *(__nv_bfloat162*)&g_UThi[oidx]     = h2a;
        *(__nv_bfloat162*)&g_UThi[oidx + 2] = h2b;
        *(__nv_bfloat162*)&g_UTlo[oidx]     = l2a;
        *(__nv_bfloat162*)&g_UTlo[oidx + 2] = l2b;
    }
}

// ============================================================================
// mma.sync GEMM. MODE 0: V[b][t][n] = (W @ uT^T)^T.  MODE 1: Y = C_eff @ S^T + D*u.
// ============================================================================
template <int MODE>
__global__ __launch_bounds__(256, 2) void mma_gemm_kernel(const float* __restrict__ U,
                                                          const float* __restrict__ Dvec,
                                                          float* __restrict__ Yout)
{
    __shared__ __align__(128) __nv_bfloat16 sA[2][128 * 32];
    __shared__ __align__(128) __nv_bfloat16 sB[2][128 * 32];

    int tid = threadIdx.x, lid = tid & 31, wid = tid >> 5;
    int warp_m = wid & 1, warp_t = wid >> 1;
    int b = blockIdx.z, t0 = blockIdx.x * 128, m0 = blockIdx.y * 128;

    const __nv_bfloat16* Ahi = (MODE == 0) ? g_Whi  : g_Chi;
    const __nv_bfloat16* Alo = (MODE == 0) ? g_Wlo  : g_Clo;
    const __nv_bfloat16* Bhi = (MODE == 0) ? g_UThi : g_Shi;
    const __nv_bfloat16* Blo = (MODE == 0) ? g_UTlo : g_Slo;
    long brow0 = (long)b * TLEN + t0;

    uint32_t aB[2] = { smem_u32(sA[0]), smem_u32(sA[1]) };
    uint32_t bB[2] = { smem_u32(sB[0]), smem_u32(sB[1]) };

    float acc[4][4][4];
#pragma unroll
    for (int mi = 0; mi < 4; mi++)
#pragma unroll
        for (int j = 0; j < 4; j++)
#pragma unroll
            for (int q = 0; q < 4; q++) acc[mi][j][q] = 0.f;

    int qa = tid;
    auto load_chunk = [&](int cs, int buf) {
        int pass = cs >> 3, k0 = (cs & 7) * 32;
        const __nv_bfloat16* As = (pass == 2) ? Alo : Ahi;
        const __nv_bfloat16* Bs = (pass == 1) ? Blo : Bhi;
#pragma unroll
        for (int i = 0; i < 2; i++) {
            int q = qa + i * 256;
            int r = q >> 2, ch = q & 3;
            cpa16(aB[buf] + swz64(r, ch), As + (long)(m0 + r) * 256 + k0 + ch * 8);
        }
#pragma unroll
        for (int i = 0; i < 2; i++) {
            int q = qa + i * 256;
            int r = q >> 2, ch = q & 3;
            cpa16(bB[buf] + swz64(r, ch), Bs + (brow0 + r) * 256 + k0 + ch * 8);
        }
        cpa_commit();
    };

    load_chunk(0, 0);
    for (int cs = 0; cs < 24; cs++) {
        int buf = cs & 1;
        if (cs + 1 < 24) {
            load_chunk(cs + 1, buf ^ 1);
            asm volatile("cp.async.wait_group 1;" ::: "memory");
        } else {
            asm volatile("cp.async.wait_group 0;" ::: "memory");
        }
        __syncthreads();

#pragma unroll
        for (int kk = 0; kk < 2; kk++) {
            int chb = kk * 2 + (lid >> 4);
            uint32_t bf[2][4];
#pragma unroll
            for (int nb = 0; nb < 2; nb++) {
                int tr = warp_t * 32 + nb * 16 + (lid & 15);
                ldmx4(bf[nb], bB[buf] + swz64(tr, chb));
            }
            uint32_t af[4][4];
#pragma unroll
            for (int mi = 0; mi < 4; mi++) {
                int r = warp_m * 64 + mi * 16 + (lid & 15);
                ldmx4(af[mi], aB[buf] + swz64(r, chb));
            }
#pragma unroll
            for (int mi = 0; mi < 4; mi++)
#pragma unroll
                for (int j = 0; j < 4; j++)
                    mma_bf16(acc[mi][j], af[mi], bf[j >> 1][j & 1], bf[j >> 1][2 + (j & 1)]);
        }
        __syncthreads();
    }

    int cbase = t0 + warp_t * 32 + 2 * (lid & 3);
#pragma unroll
    for (int mi = 0; mi < 4; mi++) {
#pragma unroll
        for (int h = 0; h < 2; h++) {
            int row = m0 + warp_m * 64 + mi * 16 + (lid >> 2) + h * 8;
            if (MODE == 0) {
#pragma unroll
                for (int j = 0; j < 4; j++) {
                    long basev = ((long)b * TLEN + cbase + j * 8) * 256 + row;
                    g_V[basev]       = acc[mi][j][2 * h];
                    g_V[basev + 256] = acc[mi][j][2 * h + 1];
                }
            } else {
                float dv = Dvec[row];
                const float* urow = U    + ((long)b * DH + row) * TLEN;
                float*       yrow = Yout + ((long)b * DH + row) * TLEN;
#pragma unroll
                for (int j = 0; j < 4; j++) {
                    float2 u2 = *(const float2*)&urow[cbase + j * 8];
                    *(float2*)&yrow[cbase + j * 8] =
                        make_float2(acc[mi][j][2 * h]     + dv * u2.x,
                                    acc[mi][j][2 * h + 1] + dv * u2.y);
                }
            }
        }
    }
}

// ============================================================================
// Scan over t on V [b][t][n]. Block = 1024 threads = 128 pairs x 8 sub-chunks
// of 16 steps (LCHUNK=128). V register-cached; all-predecessor lookback via
// published LOCAL aggregates + lambda^(128j) table (no serial carry chain).
// ============================================================================
__global__ __launch_bounds__(1024, 1) void scan_kernel()
{
    __shared__ float2 sLoc[8][NPAIR];
    __shared__ float2 sExc[8][NPAIR];
    __shared__ float2 sAgg[NPAIR];
    __shared__ float2 sE[NPAIR];

    int b = blockIdx.x & 7, chunk = blockIdx.x >> 3;
    int tid = threadIdx.x, p = tid & 127, sc = tid >> 7;
    float2 lam = g_lam[p];
    float lc = lam.x, ls = lam.y;
    float2 l16 = g_lam16[p];
    long vbase = ((long)b * TLEN + chunk * LCHUNK + sc * SUB) * 256 + 2 * p;

    // phase 1: load V into registers, local sub-chunk scan from zero
    float2 v[SUB];
    float s0 = 0.f, s1 = 0.f;
#pragma unroll
    for (int t = 0; t < SUB; t++) {
        v[t] = *(const float2*)&g_V[vbase + (long)t * 256];
        float n0 = fmaf(lc, s0, fmaf(-ls, s1, v[t].x));
        float n1 = fmaf(ls, s0, fmaf( lc, s1, v[t].y));
        s0 = n0; s1 = n1;
    }
    sLoc[sc][p] = make_float2(s0, s1);
    __syncthreads();

    // combine sub-chunk carries, publish LOCAL chunk aggregate
    int idx = b * NCHUNK + chunk;
    if (tid < NPAIR) {
        float i0 = 0.f, i1 = 0.f;
#pragma unroll
        for (int k = 0; k < 8; k++) {
            sExc[k][p] = make_float2(i0, i1);
            float2 lo = sLoc[k][p];
            float a0 = fmaf(l16.x, i0, fmaf(-l16.y, i1, lo.x));
            float a1 = fmaf(l16.y, i0, fmaf( l16.x, i1, lo.y));
            i0 = a0; i1 = a1;
        }
        sAgg[p] = make_float2(i0, i1);
        __stcg(&g_agg[idx * NPAIR + p], make_float2(i0, i1));
    }
    __syncthreads();
    if (tid == 0) {
        __threadfence();
        atomicExch(&g_flag[idx], 1);
        // wait for ALL predecessor chunks of this batch
        for (int k = 0; k < chunk; k++) {
            while (atomicAdd(&g_flag[b * NCHUNK + k], 0) == 0) __nanosleep(40);
        }
    }
    __syncthreads();

    // E = sum_{k<chunk} lambda^(128*(chunk-1-k)) * A_k
    if (tid < NPAIR) {
        float e0 = 0.f, e1 = 0.f;
        for (int k = 0; k < chunk; k++) {
            float2 pw = g_lamPow[chunk - 1 - k][p];
            float2 a = __ldcg(&g_agg[(b * NCHUNK + k) * NPAIR + p]);
            e0 = fmaf(pw.x, a.x, fmaf(-pw.y, a.y, e0));
            e1 = fmaf(pw.y, a.x, fmaf( pw.x, a.y, e1));
        }
        sE[p] = make_float2(e0, e1);
    }
    __syncthreads();

    // start state = lambda^(16*sc) * E + exclusive_within(sc)
    float2 E = sE[p];
    float m0 = 1.f, m1 = 0.f;
    for (int i = 0; i < sc; i++) {
        float a0 = m0 * l16.x - m1 * l16.y;
        float a1 = m0 * l16.y + m1 * l16.x;
        m0 = a0; m1 = a1;
    }
    float2 ex = sExc[sc][p];
    s0 = fmaf(m0, E.x, fmaf(-m1, E.y, ex.x));
    s1 = fmaf(m1, E.x, fmaf( m0, E.y, ex.y));

    // phase 2: rescan from registers + emit bf16 hi/lo
#pragma unroll
    for (int t = 0; t < SUB; t++) {
        float n0 = fmaf(lc, s0, fmaf(-ls, s1, v[t].x));
        float n1 = fmaf(ls, s0, fmaf( lc, s1, v[t].y));
        s0 = n0; s1 = n1;
        __nv_bfloat162 h2, l2;
        h2.x = __float2bfloat16_rn(s0); l2.x = __float2bfloat16_rn(s0 - __bfloat162float(h2.x));
        h2.y = __float2bfloat16_rn(s1); l2.y = __float2bfloat16_rn(s1 - __bfloat162float(h2.y));
        *(__nv_bfloat162*)&g_Shi[vbase + (long)t * 256] = h2;
        *(__nv_bfloat162*)&g_Slo[vbase + (long)t * 256] = l2;
    }
}

// ============================================================================
extern "C" void kernel_launch(void* const* d_in, const int* in_sizes, int n_in,
                              void* d_out, int out_size)
{
    const float* u          = (const float*)d_in[0];
    const float* thetas_log = (const float*)d_in[1];
    const float* P_param    = (const float*)d_in[2];
    const float* B_param    = (const float*)d_in[3];
    const float* C          = (const float*)d_in[4];
    const float* Dv         = (const float*)d_in[5];
    const float* gamma_log  = (const float*)d_in[6];
    float* Y = (float*)d_out;

    setup_kernel<<<64, 256>>>(thetas_log, P_param, B_param, C, gamma_log);
    transp_kernel<<<dim3(TLEN / 64, DH / 64, BSZ), 256>>>(u);
    mma_gemm_kernel<0><<<dim3(TLEN / 128, 2, BSZ), 256>>>(nullptr, nullptr, nullptr);
    scan_kernel<<<BSZ * NCHUNK, 1024>>>();
    mma_gemm_kernel<1><<<dim3(TLEN / 128, 2, BSZ), 256>>>(u, Dv, Y);
}

// round 8
// speedup vs baseline: 1.9748x; 1.0946x over previous
#include <cuda_runtime.h>
#include <cuda_bf16.h>
#include <cstdint>

#define BSZ    8
#define TLEN   4096
#define DH     256
#define NPAIR  128
#define LCHUNK 128
#define NCHUNK (TLEN / LCHUNK)   // 32
#define SUB    32                // steps per sub-chunk (4 sub-chunks per chunk)

// ---------------- device scratch (static; no allocations) ----------------
__device__ __align__(16) __nv_bfloat16 g_Whi[DH * DH];   // W [n][d]
__device__ __align__(16) __nv_bfloat16 g_Wlo[DH * DH];
__device__ __align__(16) __nv_bfloat16 g_Chi[DH * DH];   // C_eff [dout][n]
__device__ __align__(16) __nv_bfloat16 g_Clo[DH * DH];
__device__ __align__(16) __nv_bfloat16 g_UThi[BSZ * TLEN * DH];  // u^T [b][t][d]
__device__ __align__(16) __nv_bfloat16 g_UTlo[BSZ * TLEN * DH];
__device__ __align__(16) float         g_V   [BSZ * TLEN * DH];  // [b][t][n]
__device__ __align__(16) __nv_bfloat16 g_Shi[BSZ * TLEN * DH];   // [b][t][n]
__device__ __align__(16) __nv_bfloat16 g_Slo[BSZ * TLEN * DH];
__device__ float2 g_lam  [NPAIR];            // lambda
__device__ float2 g_lam32[NPAIR];            // lambda^32
__device__ float2 g_lamPow[NCHUNK][NPAIR];   // lambda^(128*j)
__device__ float2 g_agg  [BSZ * NCHUNK * NPAIR];  // local chunk aggregates
__device__ int    g_flag [BSZ * NCHUNK];

// ---------------- PTX helpers (all sm_80+ portable) ----------------
__device__ __forceinline__ uint32_t smem_u32(const void* p) {
    uint32_t a;
    asm("{ .reg .u64 t; cvta.to.shared.u64 t, %1; cvt.u32.u64 %0, t; }" : "=r"(a) : "l"(p));
    return a;
}
__device__ __forceinline__ void cpa16(uint32_t dst, const void* src) {
    asm volatile("cp.async.cg.shared.global [%0], [%1], 16;" :: "r"(dst), "l"(src));
}
__device__ __forceinline__ void cpa_commit() { asm volatile("cp.async.commit_group;"); }

__device__ __forceinline__ void ldmx4(uint32_t* r, uint32_t addr) {
    asm volatile("ldmatrix.sync.aligned.m8n8.x4.shared.b16 {%0,%1,%2,%3}, [%4];"
                 : "=r"(r[0]), "=r"(r[1]), "=r"(r[2]), "=r"(r[3]) : "r"(addr));
}
__device__ __forceinline__ void mma_bf16(float* c, const uint32_t* a, uint32_t b0, uint32_t b1) {
    asm volatile("mma.sync.aligned.m16n8k16.row.col.f32.bf16.bf16.f32 "
                 "{%0,%1,%2,%3}, {%4,%5,%6,%7}, {%8,%9}, {%0,%1,%2,%3};"
                 : "+f"(c[0]), "+f"(c[1]), "+f"(c[2]), "+f"(c[3])
                 : "r"(a[0]), "r"(a[1]), "r"(a[2]), "r"(a[3]), "r"(b0), "r"(b1));
}
__device__ __forceinline__ uint32_t swz64(int r, int ch) {
    return (uint32_t)(r * 64 + ((ch ^ ((r >> 1) & 3)) << 4));
}

// ============================================================================
// Setup: expm(skew) per head, fold into W=[n][d] and C_eff=[dout][n] (bf16 hi/lo).
// ============================================================================
__global__ void setup_kernel(const float* __restrict__ thetas_log,
                             const float* __restrict__ P_param,
                             const float* __restrict__ B_param,
                             const float* __restrict__ C,
                             const float* __restrict__ gamma_log)
{
    int h = blockIdx.x, tid = threadIdx.x;
    __shared__ double sA[16], sEd[16], sTm[16], sTmp[16];
    __shared__ float  sRed[256], sEf[16], sNrm;
    __shared__ double sEg;

    if (h == 0 && tid < BSZ * NCHUNK) g_flag[tid] = 0;

    float part = 0.f;
    for (int i = tid; i < 1024; i += 256) {
        float v = B_param[h * 1024 + i];
        part += v * v;
    }
    sRed[tid] = part;
    __syncthreads();
    for (int s = 128; s > 0; s >>= 1) {
        if (tid < s) sRed[tid] += sRed[tid + s];
        __syncthreads();
    }
    if (tid < 16) {
        int i = tid >> 2, j = tid & 3;
        sA[tid]  = (double)P_param[h * 16 + tid] - (double)P_param[h * 16 + j * 4 + i];
        sEd[tid] = (i == j) ? 1.0 : 0.0;
        sTm[tid] = sEd[tid];
    }
    __syncthreads();
    for (int k = 1; k <= 24; ++k) {
        if (tid < 16) {
            int i = tid >> 2, j = tid & 3;
            double acc = 0.0;
#pragma unroll
            for (int m = 0; m < 4; m++) acc += sTm[i * 4 + m] * sA[m * 4 + j];
            sTmp[tid] = acc / (double)k;
        }
        __syncthreads();
        if (tid < 16) { sTm[tid] = sTmp[tid]; sEd[tid] += sTmp[tid]; }
        __syncthreads();
    }
    const double TWO_PI = 6.283185307179586476925286766559;
    if (tid == 0) {
        double gl = (double)gamma_log[h], eg = exp(gl), gamma = exp(-eg);
        sEg = eg;
        sNrm = (float)sqrt((1.0 - gamma * gamma) / (double)sRed[0]);
        for (int j = 0; j < 2; j++) {
            double th = exp((double)thetas_log[h * 2 + j]);
            int p = h * 2 + j;
            g_lam[p] = make_float2((float)(gamma * cos(th)), (float)(gamma * sin(th)));
            double g32 = exp(-32.0 * eg), a32 = fmod(32.0 * th, TWO_PI);
            g_lam32[p] = make_float2((float)(g32 * cos(a32)), (float)(g32 * sin(a32)));
        }
    }
    if (tid < 16) sEf[tid] = (float)sEd[tid];
    __syncthreads();
    // lambda^(128*q) table: one (pair, chunk) entry per thread — parallel fp64.
    if (tid < 2 * NCHUNK) {
        int j = tid & 1, q = tid >> 1;
        double th = exp((double)thetas_log[h * 2 + j]);
        double gq = exp(-128.0 * (double)q * sEg);
        double aq = fmod(128.0 * (double)q * th, TWO_PI);
        g_lamPow[q][h * 2 + j] = make_float2((float)(gq * cos(aq)), (float)(gq * sin(aq)));
    }
    float nrm = sNrm;
    for (int o = tid; o < 1024; o += 256) {
        int N = o >> 8, d = o & 255;
        float w = 0.f;
#pragma unroll
        for (int n = 0; n < 4; n++) w += sEf[N * 4 + n] * B_param[h * 1024 + n * 256 + d];
        w *= nrm;
        __nv_bfloat16 hi = __float2bfloat16_rn(w);
        __nv_bfloat16 lo = __float2bfloat16_rn(w - __bfloat162float(hi));
        g_Whi[(h * 4 + N) * 256 + d] = hi;
        g_Wlo[(h * 4 + N) * 256 + d] = lo;
    }
    for (int o = tid; o < 1024; o += 256) {
        int N = o >> 8, Do = o & 255;
        float c = 0.f;
#pragma unroll
        for (int n = 0; n < 4; n++) c += C[Do * 256 + h * 4 + n] * sEf[N * 4 + n];
        __nv_bfloat16 hi = __float2bfloat16_rn(c);
        __nv_bfloat16 lo = __float2bfloat16_rn(c - __bfloat162float(hi));
        g_Chi[Do * 256 + h * 4 + N] = hi;
        g_Clo[Do * 256 + h * 4 + N] = lo;
    }
}

// ============================================================================
// Transpose u [b][d][t] -> u^T hi/lo bf16 [b][t][d]
// ============================================================================
__global__ __launch_bounds__(256) void transp_kernel(const float* __restrict__ U)
{
    __shared__ float s[64][65];
    int b = blockIdx.z, d0 = blockIdx.y * 64, t0 = blockIdx.x * 64;
    const float* Ub = U + ((long)b * DH + d0) * TLEN;
    int tid = threadIdx.x;
#pragma unroll
    for (int i = 0; i < 4; i++) {
        int lin = tid + i * 256;
        int r = lin >> 4, c4 = (lin & 15) << 2;
        float4 v = *(const float4*)&Ub[(long)r * TLEN + t0 + c4];
        s[r][c4] = v.x; s[r][c4 + 1] = v.y; s[r][c4 + 2] = v.z; s[r][c4 + 3] = v.w;
    }
    __syncthreads();
#pragma unroll
    for (int i = 0; i < 4; i++) {
        int lin = tid + i * 256;
        int tr = lin >> 4, dc = (lin & 15) << 2;
        long oidx = ((long)b * TLEN + t0 + tr) * 256 + d0 + dc;
        __nv_bfloat162 h2a, h2b, l2a, l2b;
        float v0 = s[dc + 0][tr], v1 = s[dc + 1][tr], v2 = s[dc + 2][tr], v3 = s[dc + 3][tr];
        h2a.x = __float2bfloat16_rn(v0); l2a.x = __float2bfloat16_rn(v0 - __bfloat162float(h2a.x));
        h2a.y = __float2bfloat16_rn(v1); l2a.y = __float2bfloat16_rn(v1 - __bfloat162float(h2a.y));
        h2b.x = __float2bfloat16_rn(v2); l2b.x = __float2bfloat16_rn(v2 - __bfloat162float(h2b.x));
        h2b.y = __float2bfloat16_rn(v3); l2b.y = __float2bfloat16_rn(v3 - __bfloat162float(h2b.y));
        *(__nv_bfloat162*)&g_UThi[oidx]     = h2a;
        *(__nv_bfloat162*)&g_UThi[oidx + 2] = h2b;
        *(__nv_bfloat162*)&g_UTlo[oidx]     = l2a;
        *(__nv_bfloat162*)&g_UTlo[oidx + 2] = l2b;
    }
}

// ============================================================================
// mma.sync GEMM. MODE 0: V[b][t][n] = (W @ uT^T)^T.  MODE 1: Y = C_eff @ S^T + D*u.
// ============================================================================
template <int MODE>
__global__ __launch_bounds__(256, 2) void mma_gemm_kernel(const float* __restrict__ U,
                                                          const float* __restrict__ Dvec,
                                                          float* __restrict__ Yout)
{
    __shared__ __align__(128) __nv_bfloat16 sA[2][128 * 32];
    __shared__ __align__(128) __nv_bfloat16 sB[2][128 * 32];

    int tid = threadIdx.x, lid = tid & 31, wid = tid >> 5;
    int warp_m = wid & 1, warp_t = wid >> 1;
    int b = blockIdx.z, t0 = blockIdx.x * 128, m0 = blockIdx.y * 128;

    const __nv_bfloat16* Ahi = (MODE == 0) ? g_Whi  : g_Chi;
    const __nv_bfloat16* Alo = (MODE == 0) ? g_Wlo  : g_Clo;
    const __nv_bfloat16* Bhi = (MODE == 0) ? g_UThi : g_Shi;
    const __nv_bfloat16* Blo = (MODE == 0) ? g_UTlo : g_Slo;
    long brow0 = (long)b * TLEN + t0;

    uint32_t aB[2] = { smem_u32(sA[0]), smem_u32(sA[1]) };
    uint32_t bB[2] = { smem_u32(sB[0]), smem_u32(sB[1]) };

    float acc[4][4][4];
#pragma unroll
    for (int mi = 0; mi < 4; mi++)
#pragma unroll
        for (int j = 0; j < 4; j++)
#pragma unroll
            for (int q = 0; q < 4; q++) acc[mi][j][q] = 0.f;

    int qa = tid;
    auto load_chunk = [&](int cs, int buf) {
        int pass = cs >> 3, k0 = (cs & 7) * 32;
        const __nv_bfloat16* As = (pass == 2) ? Alo : Ahi;
        const __nv_bfloat16* Bs = (pass == 1) ? Blo : Bhi;
#pragma unroll
        for (int i = 0; i < 2; i++) {
            int q = qa + i * 256;
            int r = q >> 2, ch = q & 3;
            cpa16(aB[buf] + swz64(r, ch), As + (long)(m0 + r) * 256 + k0 + ch * 8);
        }
#pragma unroll
        for (int i = 0; i < 2; i++) {
            int q = qa + i * 256;
            int r = q >> 2, ch = q & 3;
            cpa16(bB[buf] + swz64(r, ch), Bs + (brow0 + r) * 256 + k0 + ch * 8);
        }
        cpa_commit();
    };

    load_chunk(0, 0);
    for (int cs = 0; cs < 24; cs++) {
        int buf = cs & 1;
        if (cs + 1 < 24) {
            load_chunk(cs + 1, buf ^ 1);
            asm volatile("cp.async.wait_group 1;" ::: "memory");
        } else {
            asm volatile("cp.async.wait_group 0;" ::: "memory");
        }
        __syncthreads();

#pragma unroll
        for (int kk = 0; kk < 2; kk++) {
            int chb = kk * 2 + (lid >> 4);
            uint32_t bf[2][4];
#pragma unroll
            for (int nb = 0; nb < 2; nb++) {
                int tr = warp_t * 32 + nb * 16 + (lid & 15);
                ldmx4(bf[nb], bB[buf] + swz64(tr, chb));
            }
            uint32_t af[4][4];
#pragma unroll
            for (int mi = 0; mi < 4; mi++) {
                int r = warp_m * 64 + mi * 16 + (lid & 15);
                ldmx4(af[mi], aB[buf] + swz64(r, chb));
            }
#pragma unroll
            for (int mi = 0; mi < 4; mi++)
#pragma unroll
                for (int j = 0; j < 4; j++)
                    mma_bf16(acc[mi][j], af[mi], bf[j >> 1][j & 1], bf[j >> 1][2 + (j & 1)]);
        }
        __syncthreads();
    }

    int cbase = t0 + warp_t * 32 + 2 * (lid & 3);
#pragma unroll
    for (int mi = 0; mi < 4; mi++) {
#pragma unroll
        for (int h = 0; h < 2; h++) {
            int row = m0 + warp_m * 64 + mi * 16 + (lid >> 2) + h * 8;
            if (MODE == 0) {
#pragma unroll
                for (int j = 0; j < 4; j++) {
                    long basev = ((long)b * TLEN + cbase + j * 8) * 256 + row;
                    g_V[basev]       = acc[mi][j][2 * h];
                    g_V[basev + 256] = acc[mi][j][2 * h + 1];
                }
            } else {
                float dv = Dvec[row];
                const float* urow = U    + ((long)b * DH + row) * TLEN;
                float*       yrow = Yout + ((long)b * DH + row) * TLEN;
#pragma unroll
                for (int j = 0; j < 4; j++) {
                    float2 u2 = *(const float2*)&urow[cbase + j * 8];
                    *(float2*)&yrow[cbase + j * 8] =
                        make_float2(acc[mi][j][2 * h]     + dv * u2.x,
                                    acc[mi][j][2 * h + 1] + dv * u2.y);
                }
            }
        }
    }
}

// ============================================================================
// Scan over t on V [b][t][n]. Block = 512 threads = 128 pairs x 4 sub-chunks
// of 32 steps (LCHUNK=128). 2 blocks/SM -> 256 blocks in ONE wave.
// Parallel predecessor-flag wait + parallel partial-sum lookback.
// ============================================================================
__global__ __launch_bounds__(512, 2) void scan_kernel()
{
    __shared__ float2 sLoc [4][NPAIR];
    __shared__ float2 sExc [4][NPAIR];
    __shared__ float2 sPart[4][NPAIR];
    __shared__ float2 sE[NPAIR];

    int b = blockIdx.x & 7, chunk = blockIdx.x >> 3;
    int tid = threadIdx.x, p = tid & 127, sc = tid >> 7;   // sc in 0..3
    float2 lam = g_lam[p];
    float lc = lam.x, ls = lam.y;
    float2 l32 = g_lam32[p];
    long vbase = ((long)b * TLEN + chunk * LCHUNK + sc * SUB) * 256 + 2 * p;

    // phase 1: local sub-chunk scan from zero (V read #1)
    float s0 = 0.f, s1 = 0.f;
#pragma unroll 8
    for (int t = 0; t < SUB; t++) {
        float2 v = *(const float2*)&g_V[vbase + (long)t * 256];
        float n0 = fmaf(lc, s0, fmaf(-ls, s1, v.x));
        float n1 = fmaf(ls, s0, fmaf( lc, s1, v.y));
        s0 = n0; s1 = n1;
    }
    sLoc[sc][p] = make_float2(s0, s1);
    __syncthreads();

    // combine 4 sub-chunk carries, publish LOCAL chunk aggregate
    int idx = b * NCHUNK + chunk;
    if (tid < NPAIR) {
        float i0 = 0.f, i1 = 0.f;
#pragma unroll
        for (int k = 0; k < 4; k++) {
            sExc[k][p] = make_float2(i0, i1);
            float2 lo = sLoc[k][p];
            float a0 = fmaf(l32.x, i0, fmaf(-l32.y, i1, lo.x));
            float a1 = fmaf(l32.y, i0, fmaf( l32.x, i1, lo.y));
            i0 = a0; i1 = a1;
        }
        __stcg(&g_agg[idx * NPAIR + p], make_float2(i0, i1));
    }
    __syncthreads();
    if (tid == 0) {
        __threadfence();
        atomicExch(&g_flag[idx], 1);
    }
    // parallel wait: thread k polls predecessor flag k
    if (tid < chunk) {
        while (atomicAdd(&g_flag[b * NCHUNK + tid], 0) == 0) __nanosleep(40);
    }
    __syncthreads();

    // E = sum_{k<chunk} lambda^(128*(chunk-1-k)) * A_k, partial-summed over sc
    {
        float e0 = 0.f, e1 = 0.f;
        for (int k = sc; k < chunk; k += 4) {
            float2 pw = g_lamPow[chunk - 1 - k][p];
            float2 a = __ldcg(&g_agg[(b * NCHUNK + k) * NPAIR + p]);
            e0 = fmaf(pw.x, a.x, fmaf(-pw.y, a.y, e0));
            e1 = fmaf(pw.y, a.x, fmaf( pw.x, a.y, e1));
        }
        sPart[sc][p] = make_float2(e0, e1);
    }
    __syncthreads();
    if (tid < NPAIR) {
        float2 a0 = sPart[0][p], a1 = sPart[1][p], a2 = sPart[2][p], a3 = sPart[3][p];
        sE[p] = make_float2(a0.x + a1.x + a2.x + a3.x, a0.y + a1.y + a2.y + a3.y);
    }
    __syncthreads();

    // start state = lambda^(32*sc) * E + exclusive_within(sc)
    float2 E = sE[p];
    float m0 = 1.f, m1 = 0.f;
    for (int i = 0; i < sc; i++) {
        float a0 = m0 * l32.x - m1 * l32.y;
        float a1 = m0 * l32.y + m1 * l32.x;
        m0 = a0; m1 = a1;
    }
    float2 ex = sExc[sc][p];
    s0 = fmaf(m0, E.x, fmaf(-m1, E.y, ex.x));
    s1 = fmaf(m1, E.x, fmaf( m0, E.y, ex.y));

    // phase 2: rescan (V read #2, L2-hot) + emit bf16 hi/lo
#pragma unroll 8
    for (int t = 0; t < SUB; t++) {
        float2 v = *(const float2*)&g_V[vbase + (long)t * 256];
        float n0 = fmaf(lc, s0, fmaf(-ls, s1, v.x));
        float n1 = fmaf(ls, s0, fmaf( lc, s1, v.y));
        s0 = n0; s1 = n1;
        __nv_bfloat162 h2, l2;
        h2.x = __float2bfloat16_rn(s0); l2.x = __float2bfloat16_rn(s0 - __bfloat162float(h2.x));
        h2.y = __float2bfloat16_rn(s1); l2.y = __float2bfloat16_rn(s1 - __bfloat162float(h2.y));
        *(__nv_bfloat162*)&g_Shi[vbase + (long)t * 256] = h2;
        *(__nv_bfloat162*)&g_Slo[vbase + (long)t * 256] = l2;
    }
}

// ============================================================================
extern "C" void kernel_launch(void* const* d_in, const int* in_sizes, int n_in,
                              void* d_out, int out_size)
{
    const float* u          = (const float*)d_in[0];
    const float* thetas_log = (const float*)d_in[1];
    const float* P_param    = (const float*)d_in[2];
    const float* B_param    = (const float*)d_in[3];
    const float* C          = (const float*)d_in[4];
    const float* Dv         = (const float*)d_in[5];
    const float* gamma_log  = (const float*)d_in[6];
    float* Y = (float*)d_out;

    setup_kernel<<<64, 256>>>(thetas_log, P_param, B_param, C, gamma_log);
    transp_kernel<<<dim3(TLEN / 64, DH / 64, BSZ), 256>>>(u);
    mma_gemm_kernel<0><<<dim3(TLEN / 128, 2, BSZ), 256>>>(nullptr, nullptr, nullptr);
    scan_kernel<<<BSZ * NCHUNK, 512>>>();
    mma_gemm_kernel<1><<<dim3(TLEN / 128, 2, BSZ), 256>>>(u, Dv, Y);
}

// round 10
// speedup vs baseline: 2.2336x; 1.1310x over previous
#include <cuda_runtime.h>
#include <cuda_bf16.h>
#include <cstdint>

#define BSZ    8
#define TLEN   4096
#define DH     256
#define NPAIR  128
#define LCHUNK 128
#define NCHUNK (TLEN / LCHUNK)   // 32
#define SUB    32                // steps per sub-chunk (4 sub-chunks per chunk)

// ---------------- device scratch (static; no allocations) ----------------
__device__ __align__(16) __nv_bfloat16 g_Whi[DH * DH];   // W [n][d]
__device__ __align__(16) __nv_bfloat16 g_Wlo[DH * DH];
__device__ __align__(16) __nv_bfloat16 g_Chi[DH * DH];   // C_eff [dout][n]
__device__ __align__(16) __nv_bfloat16 g_Clo[DH * DH];
__device__ __align__(16) __nv_bfloat16 g_UThi[BSZ * TLEN * DH];  // u^T [b][t][d]
__device__ __align__(16) __nv_bfloat16 g_UTlo[BSZ * TLEN * DH];
__device__ __align__(16) float         g_V   [BSZ * TLEN * DH];  // [b][t][n]
__device__ __align__(16) __nv_bfloat16 g_Shi[BSZ * TLEN * DH];   // [b][t][n]
__device__ __align__(16) __nv_bfloat16 g_Slo[BSZ * TLEN * DH];
__device__ float2 g_lam  [NPAIR];            // lambda
__device__ float2 g_lam32[NPAIR];            // lambda^32
__device__ float2 g_lamPow[NCHUNK][NPAIR];   // lambda^(128*j)
__device__ float2 g_agg  [BSZ * NCHUNK * NPAIR];  // local chunk aggregates
__device__ int    g_flag [BSZ * NCHUNK];

// ---------------- PTX helpers (all sm_80+ portable) ----------------
__device__ __forceinline__ uint32_t smem_u32(const void* p) {
    uint32_t a;
    asm("{ .reg .u64 t; cvta.to.shared.u64 t, %1; cvt.u32.u64 %0, t; }" : "=r"(a) : "l"(p));
    return a;
}
__device__ __forceinline__ void cpa16(uint32_t dst, const void* src) {
    asm volatile("cp.async.cg.shared.global [%0], [%1], 16;" :: "r"(dst), "l"(src));
}
__device__ __forceinline__ void cpa_commit() { asm volatile("cp.async.commit_group;"); }

__device__ __forceinline__ void ldmx4(uint32_t* r, uint32_t addr) {
    asm volatile("ldmatrix.sync.aligned.m8n8.x4.shared.b16 {%0,%1,%2,%3}, [%4];"
                 : "=r"(r[0]), "=r"(r[1]), "=r"(r[2]), "=r"(r[3]) : "r"(addr));
}
__device__ __forceinline__ void mma_bf16(float* c, const uint32_t* a, uint32_t b0, uint32_t b1) {
    asm volatile("mma.sync.aligned.m16n8k16.row.col.f32.bf16.bf16.f32 "
                 "{%0,%1,%2,%3}, {%4,%5,%6,%7}, {%8,%9}, {%0,%1,%2,%3};"
                 : "+f"(c[0]), "+f"(c[1]), "+f"(c[2]), "+f"(c[3])
                 : "r"(a[0]), "r"(a[1]), "r"(a[2]), "r"(a[3]), "r"(b0), "r"(b1));
}
__device__ __forceinline__ uint32_t swz64(int r, int ch) {
    return (uint32_t)(r * 64 + ((ch ^ ((r >> 1) & 3)) << 4));
}

// ============================================================================
// Setup: expm(skew) per head, fold into W=[n][d] and C_eff=[dout][n] (bf16 hi/lo).
// ============================================================================
__global__ void setup_kernel(const float* __restrict__ thetas_log,
                             const float* __restrict__ P_param,
                             const float* __restrict__ B_param,
                             const float* __restrict__ C,
                             const float* __restrict__ gamma_log)
{
    int h = blockIdx.x, tid = threadIdx.x;
    __shared__ double sA[16], sEd[16], sTm[16], sTmp[16];
    __shared__ float  sRed[256], sEf[16], sNrm;
    __shared__ double sEg;

    if (h == 0 && tid < BSZ * NCHUNK) g_flag[tid] = 0;

    float part = 0.f;
    for (int i = tid; i < 1024; i += 256) {
        float v = B_param[h * 1024 + i];
        part += v * v;
    }
    sRed[tid] = part;
    __syncthreads();
    for (int s = 128; s > 0; s >>= 1) {
        if (tid < s) sRed[tid] += sRed[tid + s];
        __syncthreads();
    }
    if (tid < 16) {
        int i = tid >> 2, j = tid & 3;
        sA[tid]  = (double)P_param[h * 16 + tid] - (double)P_param[h * 16 + j * 4 + i];
        sEd[tid] = (i == j) ? 1.0 : 0.0;
        sTm[tid] = sEd[tid];
    }
    __syncthreads();
    for (int k = 1; k <= 24; ++k) {
        if (tid < 16) {
            int i = tid >> 2, j = tid & 3;
            double acc = 0.0;
#pragma unroll
            for (int m = 0; m < 4; m++) acc += sTm[i * 4 + m] * sA[m * 4 + j];
            sTmp[tid] = acc / (double)k;
        }
        __syncthreads();
        if (tid < 16) { sTm[tid] = sTmp[tid]; sEd[tid] += sTmp[tid]; }
        __syncthreads();
    }
    const double TWO_PI = 6.283185307179586476925286766559;
    if (tid == 0) {
        double gl = (double)gamma_log[h], eg = exp(gl), gamma = exp(-eg);
        sEg = eg;
        sNrm = (float)sqrt((1.0 - gamma * gamma) / (double)sRed[0]);
        for (int j = 0; j < 2; j++) {
            double th = exp((double)thetas_log[h * 2 + j]);
            int p = h * 2 + j;
            g_lam[p] = make_float2((float)(gamma * cos(th)), (float)(gamma * sin(th)));
            double g32 = exp(-32.0 * eg), a32 = fmod(32.0 * th, TWO_PI);
            g_lam32[p] = make_float2((float)(g32 * cos(a32)), (float)(g32 * sin(a32)));
        }
    }
    if (tid < 16) sEf[tid] = (float)sEd[tid];
    __syncthreads();
    // lambda^(128*q) table: one (pair, chunk) entry per thread — parallel fp64.
    if (tid < 2 * NCHUNK) {
        int j = tid & 1, q = tid >> 1;
        double th = exp((double)thetas_log[h * 2 + j]);
        double gq = exp(-128.0 * (double)q * sEg);
        double aq = fmod(128.0 * (double)q * th, TWO_PI);
        g_lamPow[q][h * 2 + j] = make_float2((float)(gq * cos(aq)), (float)(gq * sin(aq)));
    }
    float nrm = sNrm;
    for (int o = tid; o < 1024; o += 256) {
        int N = o >> 8, d = o & 255;
        float w = 0.f;
#pragma unroll
        for (int n = 0; n < 4; n++) w += sEf[N * 4 + n] * B_param[h * 1024 + n * 256 + d];
        w *= nrm;
        __nv_bfloat16 hi = __float2bfloat16_rn(w);
        __nv_bfloat16 lo = __float2bfloat16_rn(w - __bfloat162float(hi));
        g_Whi[(h * 4 + N) * 256 + d] = hi;
        g_Wlo[(h * 4 + N) * 256 + d] = lo;
    }
    for (int o = tid; o < 1024; o += 256) {
        int N = o >> 8, Do = o & 255;
        float c = 0.f;
#pragma unroll
        for (int n = 0; n < 4; n++) c += C[Do * 256 + h * 4 + n] * sEf[N * 4 + n];
        __nv_bfloat16 hi = __float2bfloat16_rn(c);
        __nv_bfloat16 lo = __float2bfloat16_rn(c - __bfloat162float(hi));
        g_Chi[Do * 256 + h * 4 + N] = hi;
        g_Clo[Do * 256 + h * 4 + N] = lo;
    }
}

// ============================================================================
// Transpose u [b][d][t] -> u^T hi/lo bf16 [b][t][d]
// ============================================================================
__global__ __launch_bounds__(256) void transp_kernel(const float* __restrict__ U)
{
    __shared__ float s[64][65];
    int b = blockIdx.z, d0 = blockIdx.y * 64, t0 = blockIdx.x * 64;
    const float* Ub = U + ((long)b * DH + d0) * TLEN;
    int tid = threadIdx.x;
#pragma unroll
    for (int i = 0; i < 4; i++) {
        int lin = tid + i * 256;
        int r = lin >> 4, c4 = (lin & 15) << 2;
        float4 v = *(const float4*)&Ub[(long)r * TLEN + t0 + c4];
        s[r][c4] = v.x; s[r][c4 + 1] = v.y; s[r][c4 + 2] = v.z; s[r][c4 + 3] = v.w;
    }
    __syncthreads();
#pragma unroll
    for (int i = 0; i < 4; i++) {
        int lin = tid + i * 256;
        int tr = lin >> 4, dc = (lin & 15) << 2;
        long oidx = ((long)b * TLEN + t0 + tr) * 256 + d0 + dc;
        __nv_bfloat162 h2a, h2b, l2a, l2b;
        float v0 = s[dc + 0][tr], v1 = s[dc + 1][tr], v2 = s[dc + 2][tr], v3 = s[dc + 3][tr];
        h2a.x = __float2bfloat16_rn(v0); l2a.x = __float2bfloat16_rn(v0 - __bfloat162float(h2a.x));
        h2a.y = __float2bfloat16_rn(v1); l2a.y = __float2bfloat16_rn(v1 - __bfloat162float(h2a.y));
        h2b.x = __float2bfloat16_rn(v2); l2b.x = __float2bfloat16_rn(v2 - __bfloat162float(h2b.x));
        h2b.y = __float2bfloat16_rn(v3); l2b.y = __float2bfloat16_rn(v3 - __bfloat162float(h2b.y));
        *(__nv_bfloat162*)&g_UThi[oidx]     = h2a;
        *(__nv_bfloat162*)&g_UThi[oidx + 2] = h2b;
        *(__nv_bfloat162*)&g_UTlo[oidx]     = l2a;
        *(__nv_bfloat162*)&g_UTlo[oidx + 2] = l2b;
    }
}

// ============================================================================
// mma.sync GEMM. MODE 0: V[b][t][n] = (W @ uT^T)^T.  MODE 1: Y = C_eff @ S^T + D*u.
// K = 8 chunks of 32; per chunk ALL FOUR tiles (Ahi,Alo,Bhi,Blo) resident, and
// the 3 precision passes (hh, hl, lh) issue from ONE load. Syncs 48 -> 16.
// ============================================================================
template <int MODE>
__global__ __launch_bounds__(256, 2) void mma_gemm_kernel(const float* __restrict__ U,
                                                          const float* __restrict__ Dvec,
                                                          float* __restrict__ Yout)
{
    __shared__ __align__(128) __nv_bfloat16 sAhi[2][128 * 32];
    __shared__ __align__(128) __nv_bfloat16 sAlo[2][128 * 32];
    __shared__ __align__(128) __nv_bfloat16 sBhi[2][128 * 32];
    __shared__ __align__(128) __nv_bfloat16 sBlo[2][128 * 32];

    int tid = threadIdx.x, lid = tid & 31, wid = tid >> 5;
    int warp_m = wid & 1, warp_t = wid >> 1;
    int b = blockIdx.z, t0 = blockIdx.x * 128, m0 = blockIdx.y * 128;

    const __nv_bfloat16* Ahi = (MODE == 0) ? g_Whi  : g_Chi;
    const __nv_bfloat16* Alo = (MODE == 0) ? g_Wlo  : g_Clo;
    const __nv_bfloat16* Bhi = (MODE == 0) ? g_UThi : g_Shi;
    const __nv_bfloat16* Blo = (MODE == 0) ? g_UTlo : g_Slo;
    long brow0 = (long)b * TLEN + t0;

    uint32_t aHiB[2] = { smem_u32(sAhi[0]), smem_u32(sAhi[1]) };
    uint32_t aLoB[2] = { smem_u32(sAlo[0]), smem_u32(sAlo[1]) };
    uint32_t bHiB[2] = { smem_u32(sBhi[0]), smem_u32(sBhi[1]) };
    uint32_t bLoB[2] = { smem_u32(sBlo[0]), smem_u32(sBlo[1]) };

    float acc[4][4][4];
#pragma unroll
    for (int mi = 0; mi < 4; mi++)
#pragma unroll
        for (int j = 0; j < 4; j++)
#pragma unroll
            for (int q = 0; q < 4; q++) acc[mi][j][q] = 0.f;

    auto load_chunk = [&](int cs, int buf) {
        int k0 = cs * 32;
#pragma unroll
        for (int i = 0; i < 2; i++) {
            int q = tid + i * 256;
            int r = q >> 2, ch = q & 3;
            uint32_t so = swz64(r, ch);
            long aoff = (long)(m0 + r) * 256 + k0 + ch * 8;
            long boff = (brow0 + r) * 256 + k0 + ch * 8;
            cpa16(aHiB[buf] + so, Ahi + aoff);
            cpa16(aLoB[buf] + so, Alo + aoff);
            cpa16(bHiB[buf] + so, Bhi + boff);
            cpa16(bLoB[buf] + so, Blo + boff);
        }
        cpa_commit();
    };

    load_chunk(0, 0);
    for (int cs = 0; cs < 8; cs++) {
        int buf = cs & 1;
        if (cs + 1 < 8) {
            load_chunk(cs + 1, buf ^ 1);
            asm volatile("cp.async.wait_group 1;" ::: "memory");
        } else {
            asm volatile("cp.async.wait_group 0;" ::: "memory");
        }
        __syncthreads();

#pragma unroll
        for (int kk = 0; kk < 2; kk++) {
            int chb = kk * 2 + (lid >> 4);
            uint32_t bh[2][4], bl[2][4];
#pragma unroll
            for (int nb = 0; nb < 2; nb++) {
                int tr = warp_t * 32 + nb * 16 + (lid & 15);
                uint32_t so = swz64(tr, chb);
                ldmx4(bh[nb], bHiB[buf] + so);
                ldmx4(bl[nb], bLoB[buf] + so);
            }
            uint32_t af[4][4];
            // pass hh + hl with Ahi fragments
#pragma unroll
            for (int mi = 0; mi < 4; mi++) {
                int r = warp_m * 64 + mi * 16 + (lid & 15);
                ldmx4(af[mi], aHiB[buf] + swz64(r, chb));
            }
#pragma unroll
            for (int mi = 0; mi < 4; mi++)
#pragma unroll
                for (int j = 0; j < 4; j++) {
                    mma_bf16(acc[mi][j], af[mi], bh[j >> 1][j & 1], bh[j >> 1][2 + (j & 1)]);
                    mma_bf16(acc[mi][j], af[mi], bl[j >> 1][j & 1], bl[j >> 1][2 + (j & 1)]);
                }
            // pass lh with Alo fragments (overwrite af)
#pragma unroll
            for (int mi = 0; mi < 4; mi++) {
                int r = warp_m * 64 + mi * 16 + (lid & 15);
                ldmx4(af[mi], aLoB[buf] + swz64(r, chb));
            }
#pragma unroll
            for (int mi = 0; mi < 4; mi++)
#pragma unroll
                for (int j = 0; j < 4; j++)
                    mma_bf16(acc[mi][j], af[mi], bh[j >> 1][j & 1], bh[j >> 1][2 + (j & 1)]);
        }
        __syncthreads();
    }

    int cbase = t0 + warp_t * 32 + 2 * (lid & 3);
#pragma unroll
    for (int mi = 0; mi < 4; mi++) {
#pragma unroll
        for (int h = 0; h < 2; h++) {
            int row = m0 + warp_m * 64 + mi * 16 + (lid >> 2) + h * 8;
            if (MODE == 0) {
#pragma unroll
                for (int j = 0; j < 4; j++) {
                    long basev = ((long)b * TLEN + cbase + j * 8) * 256 + row;
                    g_V[basev]       = acc[mi][j][2 * h];
                    g_V[basev + 256] = acc[mi][j][2 * h + 1];
                }
            } else {
                float dv = Dvec[row];
                const float* urow = U    + ((long)b * DH + row) * TLEN;
                float*       yrow = Yout + ((long)b * DH + row) * TLEN;
#pragma unroll
                for (int j = 0; j < 4; j++) {
                    float2 u2 = *(const float2*)&urow[cbase + j * 8];
                    *(float2*)&yrow[cbase + j * 8] =
                        make_float2(acc[mi][j][2 * h]     + dv * u2.x,
                                    acc[mi][j][2 * h + 1] + dv * u2.y);
                }
            }
        }
    }
}

// ============================================================================
// Scan over t on V [b][t][n]. Block = 512 threads = 128 pairs x 4 sub-chunks
// of 32 steps (LCHUNK=128). 2 blocks/SM -> 256 blocks in ONE wave.
// Parallel predecessor-flag wait + parallel partial-sum lookback.
// ============================================================================
__global__ __launch_bounds__(512, 2) void scan_kernel()
{
    __shared__ float2 sLoc [4][NPAIR];
    __shared__ float2 sExc [4][NPAIR];
    __shared__ float2 sPart[4][NPAIR];
    __shared__ float2 sE[NPAIR];

    int b = blockIdx.x & 7, chunk = blockIdx.x >> 3;
    int tid = threadIdx.x, p = tid & 127, sc = tid >> 7;   // sc in 0..3
    float2 lam = g_lam[p];
    float lc = lam.x, ls = lam.y;
    float2 l32 = g_lam32[p];
    long vbase = ((long)b * TLEN + chunk * LCHUNK + sc * SUB) * 256 + 2 * p;

    // phase 1: local sub-chunk scan from zero (V read #1)
    float s0 = 0.f, s1 = 0.f;
#pragma unroll 8
    for (int t = 0; t < SUB; t++) {
        float2 v = *(const float2*)&g_V[vbase + (long)t * 256];
        float n0 = fmaf(lc, s0, fmaf(-ls, s1, v.x));
        float n1 = fmaf(ls, s0, fmaf( lc, s1, v.y));
        s0 = n0; s1 = n1;
    }
    sLoc[sc][p] = make_float2(s0, s1);
    __syncthreads();

    // combine 4 sub-chunk carries, publish LOCAL chunk aggregate
    int idx = b * NCHUNK + chunk;
    if (tid < NPAIR) {
        float i0 = 0.f, i1 = 0.f;
#pragma unroll
        for (int k = 0; k < 4; k++) {
            sExc[k][p] = make_float2(i0, i1);
            float2 lo = sLoc[k][p];
            float a0 = fmaf(l32.x, i0, fmaf(-l32.y, i1, lo.x));
            float a1 = fmaf(l32.y, i0, fmaf( l32.x, i1, lo.y));
            i0 = a0; i1 = a1;
        }
        __stcg(&g_agg[idx * NPAIR + p], make_float2(i0, i1));
    }
    __syncthreads();
    if (tid == 0) {
        __threadfence();
        atomicExch(&g_flag[idx], 1);
    }
    // parallel wait: thread k polls predecessor flag k
    if (tid < chunk) {
        while (atomicAdd(&g_flag[b * NCHUNK + tid], 0) == 0) __nanosleep(40);
    }
    __syncthreads();

    // E = sum_{k<chunk} lambda^(128*(chunk-1-k)) * A_k, partial-summed over sc
    {
        float e0 = 0.f, e1 = 0.f;
        for (int k = sc; k < chunk; k += 4) {
            float2 pw = g_lamPow[chunk - 1 - k][p];
            float2 a = __ldcg(&g_agg[(b * NCHUNK + k) * NPAIR + p]);
            e0 = fmaf(pw.x, a.x, fmaf(-pw.y, a.y, e0));
            e1 = fmaf(pw.y, a.x, fmaf( pw.x, a.y, e1));
        }
        sPart[sc][p] = make_float2(e0, e1);
    }
    __syncthreads();
    if (tid < NPAIR) {
        float2 a0 = sPart[0][p], a1 = sPart[1][p], a2 = sPart[2][p], a3 = sPart[3][p];
        sE[p] = make_float2(a0.x + a1.x + a2.x + a3.x, a0.y + a1.y + a2.y + a3.y);
    }
    __syncthreads();

    // start state = lambda^(32*sc) * E + exclusive_within(sc)
    float2 E = sE[p];
    float m0 = 1.f, m1 = 0.f;
    for (int i = 0; i < sc; i++) {
        float a0 = m0 * l32.x - m1 * l32.y;
        float a1 = m0 * l32.y + m1 * l32.x;
        m0 = a0; m1 = a1;
    }
    float2 ex = sExc[sc][p];
    s0 = fmaf(m0, E.x, fmaf(-m1, E.y, ex.x));
    s1 = fmaf(m1, E.x, fmaf( m0, E.y, ex.y));

    // phase 2: rescan (V read #2, L2-hot) + emit bf16 hi/lo
#pragma unroll 8
    for (int t = 0; t < SUB; t++) {
        float2 v = *(const float2*)&g_V[vbase + (long)t * 256];
        float n0 = fmaf(lc, s0, fmaf(-ls, s1, v.x));
        float n1 = fmaf(ls, s0, fmaf( lc, s1, v.y));
        s0 = n0; s1 = n1;
        __nv_bfloat162 h2, l2;
        h2.x = __float2bfloat16_rn(s0); l2.x = __float2bfloat16_rn(s0 - __bfloat162float(h2.x));
        h2.y = __float2bfloat16_rn(s1); l2.y = __float2bfloat16_rn(s1 - __bfloat162float(h2.y));
        *(__nv_bfloat162*)&g_Shi[vbase + (long)t * 256] = h2;
        *(__nv_bfloat162*)&g_Slo[vbase + (long)t * 256] = l2;
    }
}

// ============================================================================
extern "C" void kernel_launch(void* const* d_in, const int* in_sizes, int n_in,
                              void* d_out, int out_size)
{
    const float* u          = (const float*)d_in[0];
    const float* thetas_log = (const float*)d_in[1];
    const float* P_param    = (const float*)d_in[2];
    const float* B_param    = (const float*)d_in[3];
    const float* C          = (const float*)d_in[4];
    const float* Dv         = (const float*)d_in[5];
    const float* gamma_log  = (const float*)d_in[6];
    float* Y = (float*)d_out;

    setup_kernel<<<64, 256>>>(thetas_log, P_param, B_param, C, gamma_log);
    transp_kernel<<<dim3(TLEN / 64, DH / 64, BSZ), 256>>>(u);
    mma_gemm_kernel<0><<<dim3(TLEN / 128, 2, BSZ), 256>>>(nullptr, nullptr, nullptr);
    scan_kernel<<<BSZ * NCHUNK, 512>>>();
    mma_gemm_kernel<1><<<dim3(TLEN / 128, 2, BSZ), 256>>>(u, Dv, Y);
}

// round 12
// speedup vs baseline: 2.3264x; 1.0415x over previous
#include <cuda_runtime.h>
#include <cuda_bf16.h>
#include <cstdint>

#define BSZ    8
#define TLEN   4096
#define DH     256
#define NPAIR  128
#define LCHUNK 128
#define NCHUNK (TLEN / LCHUNK)   // 32
#define SUB    16                // steps per sub-chunk (8 sub-chunks per chunk)

// ---------------- device scratch (static; no allocations) ----------------
__device__ __align__(16) __nv_bfloat16 g_Whi[DH * DH];   // W [n][d]
__device__ __align__(16) __nv_bfloat16 g_Wlo[DH * DH];
__device__ __align__(16) __nv_bfloat16 g_Chi[DH * DH];   // C_eff [dout][n]
__device__ __align__(16) __nv_bfloat16 g_Clo[DH * DH];
__device__ __align__(16) __nv_bfloat16 g_UThi[BSZ * TLEN * DH];  // u^T [b][t][d]
__device__ __align__(16) __nv_bfloat16 g_UTlo[BSZ * TLEN * DH];
__device__ __align__(16) float         g_V   [BSZ * TLEN * DH];  // [b][t][n]
__device__ __align__(16) __nv_bfloat16 g_Shi[BSZ * TLEN * DH];   // [b][t][n]
__device__ __align__(16) __nv_bfloat16 g_Slo[BSZ * TLEN * DH];
__device__ float2 g_lam  [NPAIR];            // lambda
__device__ float2 g_lam16[NPAIR];            // lambda^16
__device__ float2 g_lamPow[NCHUNK][NPAIR];   // lambda^(128*j)
__device__ __align__(16) float2 g_agg[BSZ * NCHUNK * NPAIR];  // chunk aggregates
__device__ int    g_flag [BSZ * NCHUNK];

// ---------------- PTX helpers (all sm_80+ portable) ----------------
__device__ __forceinline__ uint32_t smem_u32(const void* p) {
    uint32_t a;
    asm("{ .reg .u64 t; cvta.to.shared.u64 t, %1; cvt.u32.u64 %0, t; }" : "=r"(a) : "l"(p));
    return a;
}
__device__ __forceinline__ void cpa16(uint32_t dst, const void* src) {
    asm volatile("cp.async.cg.shared.global [%0], [%1], 16;" :: "r"(dst), "l"(src));
}
__device__ __forceinline__ void cpa_commit() { asm volatile("cp.async.commit_group;"); }

__device__ __forceinline__ void ldmx4(uint32_t* r, uint32_t addr) {
    asm volatile("ldmatrix.sync.aligned.m8n8.x4.shared.b16 {%0,%1,%2,%3}, [%4];"
                 : "=r"(r[0]), "=r"(r[1]), "=r"(r[2]), "=r"(r[3]) : "r"(addr));
}
__device__ __forceinline__ void mma_bf16(float* c, const uint32_t* a, uint32_t b0, uint32_t b1) {
    asm volatile("mma.sync.aligned.m16n8k16.row.col.f32.bf16.bf16.f32 "
                 "{%0,%1,%2,%3}, {%4,%5,%6,%7}, {%8,%9}, {%0,%1,%2,%3};"
                 : "+f"(c[0]), "+f"(c[1]), "+f"(c[2]), "+f"(c[3])
                 : "r"(a[0]), "r"(a[1]), "r"(a[2]), "r"(a[3]), "r"(b0), "r"(b1));
}
__device__ __forceinline__ uint32_t swz64(int r, int ch) {
    return (uint32_t)(r * 64 + ((ch ^ ((r >> 1) & 3)) << 4));
}

// ============================================================================
// Fused init: blocks 0..63 do per-head setup (expm fold, lambdas, flags);
// blocks 64.. do the u transpose -> bf16 hi/lo [b][t][d]. Independent work.
// ============================================================================
__global__ __launch_bounds__(256) void init_kernel(const float* __restrict__ U,
                                                   const float* __restrict__ thetas_log,
                                                   const float* __restrict__ P_param,
                                                   const float* __restrict__ B_param,
                                                   const float* __restrict__ C,
                                                   const float* __restrict__ gamma_log)
{
    int tid = threadIdx.x;
    if (blockIdx.x < 64) {
        int h = blockIdx.x;
        __shared__ double sA[16], sEd[16], sTm[16], sTmp[16];
        __shared__ float  sRed[256], sEf[16], sNrm;
        __shared__ double sEg;

        if (h == 0 && tid < BSZ * NCHUNK) g_flag[tid] = 0;

        float part = 0.f;
        for (int i = tid; i < 1024; i += 256) {
            float v = B_param[h * 1024 + i];
            part += v * v;
        }
        sRed[tid] = part;
        __syncthreads();
        for (int s = 128; s > 0; s >>= 1) {
            if (tid < s) sRed[tid] += sRed[tid + s];
            __syncthreads();
        }
        if (tid < 16) {
            int i = tid >> 2, j = tid & 3;
            sA[tid]  = (double)P_param[h * 16 + tid] - (double)P_param[h * 16 + j * 4 + i];
            sEd[tid] = (i == j) ? 1.0 : 0.0;
            sTm[tid] = sEd[tid];
        }
        __syncthreads();
        for (int k = 1; k <= 24; ++k) {
            if (tid < 16) {
                int i = tid >> 2, j = tid & 3;
                double acc = 0.0;
#pragma unroll
                for (int m = 0; m < 4; m++) acc += sTm[i * 4 + m] * sA[m * 4 + j];
                sTmp[tid] = acc / (double)k;
            }
            __syncthreads();
            if (tid < 16) { sTm[tid] = sTmp[tid]; sEd[tid] += sTmp[tid]; }
            __syncthreads();
        }
        const double TWO_PI = 6.283185307179586476925286766559;
        if (tid == 0) {
            double gl = (double)gamma_log[h], eg = exp(gl), gamma = exp(-eg);
            sEg = eg;
            sNrm = (float)sqrt((1.0 - gamma * gamma) / (double)sRed[0]);
            for (int j = 0; j < 2; j++) {
                double th = exp((double)thetas_log[h * 2 + j]);
                int p = h * 2 + j;
                g_lam[p] = make_float2((float)(gamma * cos(th)), (float)(gamma * sin(th)));
                double g16 = exp(-16.0 * eg), a16 = fmod(16.0 * th, TWO_PI);
                g_lam16[p] = make_float2((float)(g16 * cos(a16)), (float)(g16 * sin(a16)));
            }
        }
        if (tid < 16) sEf[tid] = (float)sEd[tid];
        __syncthreads();
        if (tid < 2 * NCHUNK) {
            int j = tid & 1, q = tid >> 1;
            double th = exp((double)thetas_log[h * 2 + j]);
            double gq = exp(-128.0 * (double)q * sEg);
            double aq = fmod(128.0 * (double)q * th, TWO_PI);
            g_lamPow[q][h * 2 + j] = make_float2((float)(gq * cos(aq)), (float)(gq * sin(aq)));
        }
        float nrm = sNrm;
        for (int o = tid; o < 1024; o += 256) {
            int N = o >> 8, d = o & 255;
            float w = 0.f;
#pragma unroll
            for (int n = 0; n < 4; n++) w += sEf[N * 4 + n] * B_param[h * 1024 + n * 256 + d];
            w *= nrm;
            __nv_bfloat16 hi = __float2bfloat16_rn(w);
            __nv_bfloat16 lo = __float2bfloat16_rn(w - __bfloat162float(hi));
            g_Whi[(h * 4 + N) * 256 + d] = hi;
            g_Wlo[(h * 4 + N) * 256 + d] = lo;
        }
        for (int o = tid; o < 1024; o += 256) {
            int N = o >> 8, Do = o & 255;
            float c = 0.f;
#pragma unroll
            for (int n = 0; n < 4; n++) c += C[Do * 256 + h * 4 + n] * sEf[N * 4 + n];
            __nv_bfloat16 hi = __float2bfloat16_rn(c);
            __nv_bfloat16 lo = __float2bfloat16_rn(c - __bfloat162float(hi));
            g_Chi[Do * 256 + h * 4 + N] = hi;
            g_Clo[Do * 256 + h * 4 + N] = lo;
        }
    } else {
        // transpose tile: linear id -> (b, d0, t0)
        __shared__ float s[64][65];
        int lin = blockIdx.x - 64;          // 0..2047
        int b  = lin >> 8;                  // 8
        int d0 = ((lin >> 6) & 3) * 64;     // 4
        int t0 = (lin & 63) * 64;           // 64
        const float* Ub = U + ((long)b * DH + d0) * TLEN;
#pragma unroll
        for (int i = 0; i < 4; i++) {
            int q = tid + i * 256;
            int r = q >> 4, c4 = (q & 15) << 2;
            float4 v = *(const float4*)&Ub[(long)r * TLEN + t0 + c4];
            s[r][c4] = v.x; s[r][c4 + 1] = v.y; s[r][c4 + 2] = v.z; s[r][c4 + 3] = v.w;
        }
        __syncthreads();
#pragma unroll
        for (int i = 0; i < 4; i++) {
            int q = tid + i * 256;
            int tr = q >> 4, dc = (q & 15) << 2;
            long oidx = ((long)b * TLEN + t0 + tr) * 256 + d0 + dc;
            __nv_bfloat162 h2a, h2b, l2a, l2b;
            float v0 = s[dc + 0][tr], v1 = s[dc + 1][tr], v2 = s[dc + 2][tr], v3 = s[dc + 3][tr];
            h2a.x = __float2bfloat16_rn(v0); l2a.x = __float2bfloat16_rn(v0 - __bfloat162float(h2a.x));
            h2a.y = __float2bfloat16_rn(v1); l2a.y = __float2bfloat16_rn(v1 - __bfloat162float(h2a.y));
            h2b.x = __float2bfloat16_rn(v2); l2b.x = __float2bfloat16_rn(v2 - __bfloat162float(h2b.x));
            h2b.y = __float2bfloat16_rn(v3); l2b.y = __float2bfloat16_rn(v3 - __bfloat162float(h2b.y));
            *(__nv_bfloat162*)&g_UThi[oidx]     = h2a;
            *(__nv_bfloat162*)&g_UThi[oidx + 2] = h2b;
            *(__nv_bfloat162*)&g_UTlo[oidx]     = l2a;
            *(__nv_bfloat162*)&g_UTlo[oidx + 2] = l2b;
        }
    }
}

// ============================================================================
// mma.sync GEMM. MODE 0: V[b][t][n] = (W @ uT^T)^T.  MODE 1: Y = C_eff @ S^T + D*u.
// K = 8 chunks of 32; all four hi/lo tiles resident; 3 passes from one load.
// (UNCHANGED from round 10 — protected win.)
// ============================================================================
template <int MODE>
__global__ __launch_bounds__(256, 2) void mma_gemm_kernel(const float* __restrict__ U,
                                                          const float* __restrict__ Dvec,
                                                          float* __restrict__ Yout)
{
    __shared__ __align__(128) __nv_bfloat16 sAhi[2][128 * 32];
    __shared__ __align__(128) __nv_bfloat16 sAlo[2][128 * 32];
    __shared__ __align__(128) __nv_bfloat16 sBhi[2][128 * 32];
    __shared__ __align__(128) __nv_bfloat16 sBlo[2][128 * 32];

    int tid = threadIdx.x, lid = tid & 31, wid = tid >> 5;
    int warp_m = wid & 1, warp_t = wid >> 1;
    int b = blockIdx.z, t0 = blockIdx.x * 128, m0 = blockIdx.y * 128;

    const __nv_bfloat16* Ahi = (MODE == 0) ? g_Whi  : g_Chi;
    const __nv_bfloat16* Alo = (MODE == 0) ? g_Wlo  : g_Clo;
    const __nv_bfloat16* Bhi = (MODE == 0) ? g_UThi : g_Shi;
    const __nv_bfloat16* Blo = (MODE == 0) ? g_UTlo : g_Slo;
    long brow0 = (long)b * TLEN + t0;

    uint32_t aHiB[2] = { smem_u32(sAhi[0]), smem_u32(sAhi[1]) };
    uint32_t aLoB[2] = { smem_u32(sAlo[0]), smem_u32(sAlo[1]) };
    uint32_t bHiB[2] = { smem_u32(sBhi[0]), smem_u32(sBhi[1]) };
    uint32_t bLoB[2] = { smem_u32(sBlo[0]), smem_u32(sBlo[1]) };

    float acc[4][4][4];
#pragma unroll
    for (int mi = 0; mi < 4; mi++)
#pragma unroll
        for (int j = 0; j < 4; j++)
#pragma unroll
            for (int q = 0; q < 4; q++) acc[mi][j][q] = 0.f;

    auto load_chunk = [&](int cs, int buf) {
        int k0 = cs * 32;
#pragma unroll
        for (int i = 0; i < 2; i++) {
            int q = tid + i * 256;
            int r = q >> 2, ch = q & 3;
            uint32_t so = swz64(r, ch);
            long aoff = (long)(m0 + r) * 256 + k0 + ch * 8;
            long boff = (brow0 + r) * 256 + k0 + ch * 8;
            cpa16(aHiB[buf] + so, Ahi + aoff);
            cpa16(aLoB[buf] + so, Alo + aoff);
            cpa16(bHiB[buf] + so, Bhi + boff);
            cpa16(bLoB[buf] + so, Blo + boff);
        }
        cpa_commit();
    };

    load_chunk(0, 0);
    for (int cs = 0; cs < 8; cs++) {
        int buf = cs & 1;
        if (cs + 1 < 8) {
            load_chunk(cs + 1, buf ^ 1);
            asm volatile("cp.async.wait_group 1;" ::: "memory");
        } else {
            asm volatile("cp.async.wait_group 0;" ::: "memory");
        }
        __syncthreads();

#pragma unroll
        for (int kk = 0; kk < 2; kk++) {
            int chb = kk * 2 + (lid >> 4);
            uint32_t bh[2][4], bl[2][4];
#pragma unroll
            for (int nb = 0; nb < 2; nb++) {
                int tr = warp_t * 32 + nb * 16 + (lid & 15);
                uint32_t so = swz64(tr, chb);
                ldmx4(bh[nb], bHiB[buf] + so);
                ldmx4(bl[nb], bLoB[buf] + so);
            }
            uint32_t af[4][4];
#pragma unroll
            for (int mi = 0; mi < 4; mi++) {
                int r = warp_m * 64 + mi * 16 + (lid & 15);
                ldmx4(af[mi], aHiB[buf] + swz64(r, chb));
            }
#pragma unroll
            for (int mi = 0; mi < 4; mi++)
#pragma unroll
                for (int j = 0; j < 4; j++) {
                    mma_bf16(acc[mi][j], af[mi], bh[j >> 1][j & 1], bh[j >> 1][2 + (j & 1)]);
                    mma_bf16(acc[mi][j], af[mi], bl[j >> 1][j & 1], bl[j >> 1][2 + (j & 1)]);
                }
#pragma unroll
            for (int mi = 0; mi < 4; mi++) {
                int r = warp_m * 64 + mi * 16 + (lid & 15);
                ldmx4(af[mi], aLoB[buf] + swz64(r, chb));
            }
#pragma unroll
            for (int mi = 0; mi < 4; mi++)
#pragma unroll
                for (int j = 0; j < 4; j++)
                    mma_bf16(acc[mi][j], af[mi], bh[j >> 1][j & 1], bh[j >> 1][2 + (j & 1)]);
        }
        __syncthreads();
    }

    int cbase = t0 + warp_t * 32 + 2 * (lid & 3);
#pragma unroll
    for (int mi = 0; mi < 4; mi++) {
#pragma unroll
        for (int h = 0; h < 2; h++) {
            int row = m0 + warp_m * 64 + mi * 16 + (lid >> 2) + h * 8;
            if (MODE == 0) {
#pragma unroll
                for (int j = 0; j < 4; j++) {
                    long basev = ((long)b * TLEN + cbase + j * 8) * 256 + row;
                    g_V[basev]       = acc[mi][j][2 * h];
                    g_V[basev + 256] = acc[mi][j][2 * h + 1];
                }
            } else {
                float dv = Dvec[row];
                const float* urow = U    + ((long)b * DH + row) * TLEN;
                float*       yrow = Yout + ((long)b * DH + row) * TLEN;
#pragma unroll
                for (int j = 0; j < 4; j++) {
                    float2 u2 = *(const float2*)&urow[cbase + j * 8];
                    *(float2*)&yrow[cbase + j * 8] =
                        make_float2(acc[mi][j][2 * h]     + dv * u2.x,
                                    acc[mi][j][2 * h + 1] + dv * u2.y);
                }
            }
        }
    }
}

// ============================================================================
// Scan over t on V [b][t][n]. Block = 512 threads = 64 pair-groups (2 pairs
// per thread, float4 loads -> 2 independent complex chains for ILP) x 8
// sub-chunks of 16 steps. Parallel flag wait + partial-sum lookback.
// ============================================================================
__global__ __launch_bounds__(512, 2) void scan_kernel()
{
    __shared__ float4 sLoc [8][64];
    __shared__ float4 sExc [8][64];
    __shared__ float4 sPart[8][64];
    __shared__ float4 sE[64];

    int b = blockIdx.x & 7, chunk = blockIdx.x >> 3;
    int tid = threadIdx.x, g = tid & 63, sc = tid >> 6;   // sc in 0..7
    float2 lamA = g_lam[2 * g],   lamB = g_lam[2 * g + 1];
    float2 l16A = g_lam16[2 * g], l16B = g_lam16[2 * g + 1];
    long vbase = ((long)b * TLEN + chunk * LCHUNK + sc * SUB) * 256 + 4 * g;

    // phase 1: two interleaved local chains from zero (V read #1)
    float a0 = 0.f, a1 = 0.f, c0 = 0.f, c1 = 0.f;
#pragma unroll
    for (int t = 0; t < SUB; t++) {
        float4 v = *(const float4*)&g_V[vbase + (long)t * 256];
        float na0 = fmaf(lamA.x, a0, fmaf(-lamA.y, a1, v.x));
        float na1 = fmaf(lamA.y, a0, fmaf( lamA.x, a1, v.y));
        float nc0 = fmaf(lamB.x, c0, fmaf(-lamB.y, c1, v.z));
        float nc1 = fmaf(lamB.y, c0, fmaf( lamB.x, c1, v.w));
        a0 = na0; a1 = na1; c0 = nc0; c1 = nc1;
    }
    sLoc[sc][g] = make_float4(a0, a1, c0, c1);
    __syncthreads();

    // combine 8 sub-chunk carries, publish LOCAL chunk aggregate
    int idx = b * NCHUNK + chunk;
    if (tid < 64) {
        float i0 = 0.f, i1 = 0.f, j0 = 0.f, j1 = 0.f;
#pragma unroll
        for (int k = 0; k < 8; k++) {
            sExc[k][g] = make_float4(i0, i1, j0, j1);
            float4 lo = sLoc[k][g];
            float x0 = fmaf(l16A.x, i0, fmaf(-l16A.y, i1, lo.x));
            float x1 = fmaf(l16A.y, i0, fmaf( l16A.x, i1, lo.y));
            float y0 = fmaf(l16B.x, j0, fmaf(-l16B.y, j1, lo.z));
            float y1 = fmaf(l16B.y, j0, fmaf( l16B.x, j1, lo.w));
            i0 = x0; i1 = x1; j0 = y0; j1 = y1;
        }
        __stcg((float4*)&g_agg[idx * NPAIR + 2 * g], make_float4(i0, i1, j0, j1));
    }
    __syncthreads();
    if (tid == 0) {
        __threadfence();
        atomicExch(&g_flag[idx], 1);
    }
    // parallel wait: thread k polls predecessor flag k
    if (tid < chunk) {
        while (atomicAdd(&g_flag[b * NCHUNK + tid], 0) == 0) __nanosleep(40);
    }
    __syncthreads();

    // E = sum_{k<chunk} lambda^(128*(chunk-1-k)) * A_k, partial-summed over sc
    {
        float e0 = 0.f, e1 = 0.f, f0 = 0.f, f1 = 0.f;
        for (int k = sc; k < chunk; k += 8) {
            float2 pwA = g_lamPow[chunk - 1 - k][2 * g];
            float2 pwB = g_lamPow[chunk - 1 - k][2 * g + 1];
            float4 a = __ldcg((const float4*)&g_agg[(b * NCHUNK + k) * NPAIR + 2 * g]);
            e0 = fmaf(pwA.x, a.x, fmaf(-pwA.y, a.y, e0));
            e1 = fmaf(pwA.y, a.x, fmaf( pwA.x, a.y, e1));
            f0 = fmaf(pwB.x, a.z, fmaf(-pwB.y, a.w, f0));
            f1 = fmaf(pwB.y, a.z, fmaf( pwB.x, a.w, f1));
        }
        sPart[sc][g] = make_float4(e0, e1, f0, f1);
    }
    __syncthreads();
    if (tid < 64) {
        float4 s = make_float4(0.f, 0.f, 0.f, 0.f);
#pragma unroll
        for (int k = 0; k < 8; k++) {
            float4 p = sPart[k][g];
            s.x += p.x; s.y += p.y; s.z += p.z; s.w += p.w;
        }
        sE[g] = s;
    }
    __syncthreads();

    // start state = lambda^(16*sc) * E + exclusive_within(sc)
    float4 E = sE[g];
    float mA0 = 1.f, mA1 = 0.f, mB0 = 1.f, mB1 = 0.f;
    for (int i = 0; i < sc; i++) {
        float x0 = mA0 * l16A.x - mA1 * l16A.y, x1 = mA0 * l16A.y + mA1 * l16A.x;
        float y0 = mB0 * l16B.x - mB1 * l16B.y, y1 = mB0 * l16B.y + mB1 * l16B.x;
        mA0 = x0; mA1 = x1; mB0 = y0; mB1 = y1;
    }
    float4 ex = sExc[sc][g];
    a0 = fmaf(mA0, E.x, fmaf(-mA1, E.y, ex.x));
    a1 = fmaf(mA1, E.x, fmaf( mA0, E.y, ex.y));
    c0 = fmaf(mB0, E.z, fmaf(-mB1, E.w, ex.z));
    c1 = fmaf(mB1, E.z, fmaf( mB0, E.w, ex.w));

    // phase 2: rescan (V read #2, L2-hot) + emit bf16 hi/lo (8B stores)
#pragma unroll
    for (int t = 0; t < SUB; t++) {
        float4 v = *(const float4*)&g_V[vbase + (long)t * 256];
        float na0 = fmaf(lamA.x, a0, fmaf(-lamA.y, a1, v.x));
        float na1 = fmaf(lamA.y, a0, fmaf( lamA.x, a1, v.y));
        float nc0 = fmaf(lamB.x, c0, fmaf(-lamB.y, c1, v.z));
        float nc1 = fmaf(lamB.y, c0, fmaf( lamB.x, c1, v.w));
        a0 = na0; a1 = na1; c0 = nc0; c1 = nc1;
        __nv_bfloat162 hA, hB, lA, lB;
        hA.x = __float2bfloat16_rn(a0); lA.x = __float2bfloat16_rn(a0 - __bfloat162float(hA.x));
        hA.y = __float2bfloat16_rn(a1); lA.y = __float2bfloat16_rn(a1 - __bfloat162float(hA.y));
        hB.x = __float2bfloat16_rn(c0); lB.x = __float2bfloat16_rn(c0 - __bfloat162float(hB.x));
        hB.y = __float2bfloat16_rn(c1); lB.y = __float2bfloat16_rn(c1 - __bfloat162float(hB.y));
        uint2 hv, lv;
        hv.x = *(uint32_t*)&hA; hv.y = *(uint32_t*)&hB;
        lv.x = *(uint32_t*)&lA; lv.y = *(uint32_t*)&lB;
        *(uint2*)&g_Shi[vbase + (long)t * 256] = hv;
        *(uint2*)&g_Slo[vbase + (long)t * 256] = lv;
    }
}

// ============================================================================
extern "C" void kernel_launch(void* const* d_in, const int* in_sizes, int n_in,
                              void* d_out, int out_size)
{
    const float* u          = (const float*)d_in[0];
    const float* thetas_log = (const float*)d_in[1];
    const float* P_param    = (const float*)d_in[2];
    const float* B_param    = (const float*)d_in[3];
    const float* C          = (const float*)d_in[4];
    const float* Dv         = (const float*)d_in[5];
    const float* gamma_log  = (const float*)d_in[6];
    float* Y = (float*)d_out;

    init_kernel<<<64 + 2048, 256>>>(u, thetas_log, P_param, B_param, C, gamma_log);
    mma_gemm_kernel<0><<<dim3(TLEN / 128, 2, BSZ), 256>>>(nullptr, nullptr, nullptr);
    scan_kernel<<<BSZ * NCHUNK, 512>>>();
    mma_gemm_kernel<1><<<dim3(TLEN / 128, 2, BSZ), 256>>>(u, Dv, Y);
}